// round 5
// baseline (speedup 1.0000x reference)
#include <cuda_runtime.h>
#include <math.h>
#include <stdint.h>

#define NC    2048
#define DD    1024
#define HD2   512
#define BB    2
#define HH    8
#define HDIM  128
#define D3    3072
#define INDIM 512

// ----------------------------- device scratch -----------------------------
__device__ float g_ampr0[NC*2*DD];
__device__ float g_ampi0[NC*2*DD];
__device__ float g_ampr1[NC*2*DD];
__device__ float g_ampi1[NC*2*DD];
__device__ float g_probs[NC];
__device__ float g_ph[NC];
__device__ float g_cells[NC*DD];
__device__ float g_fmean[8*DD];
__device__ float g_xproj[BB*DD];
__device__ float g_cellsB[BB*NC*DD];
__device__ float g_qkv[(size_t)BB*NC*D3];
__device__ float g_scores[(size_t)BB*HH*NC*NC];   // raw exp(S), 256 MiB
__device__ float g_rowsum[BB*HH*NC];
__device__ float g_av[(size_t)BB*NC*DD];
__device__ float g_tmp[(size_t)BB*NC*DD];
__device__ float g_part1[BB*NC];
__device__ float g_part2[BB*NC];
__device__ float g_xmean;
__device__ float g_ptot;
__device__ float g_tension;

// ----------------------------- small kernels ------------------------------
__global__ void k_xmean(const float* __restrict__ x, int n) {
    __shared__ float red[256];
    float s = 0.f;
    for (int i = threadIdx.x; i < n; i += 256) s += x[i];
    red[threadIdx.x] = s; __syncthreads();
    for (int st = 128; st > 0; st >>= 1) {
        if (threadIdx.x < st) red[threadIdx.x] += red[threadIdx.x + st];
        __syncthreads();
    }
    if (threadIdx.x == 0) { g_xmean = red[0] / (float)n; g_tension = 0.f; }
}

// fused quantum-walk step + probs/phase reduction (norm skipped: scale-inv)
__global__ void k_walkp(const float* __restrict__ inr, const float* __restrict__ ini,
                        float* __restrict__ outr, float* __restrict__ outi,
                        const float* __restrict__ cr, const float* __restrict__ ci) {
    __shared__ float rp[256], rh[256];
    int n = blockIdx.x;
    float c00r=cr[0], c01r=cr[1], c10r=cr[2], c11r=cr[3];
    float c00i=ci[0], c01i=ci[1], c10i=ci[2], c11i=ci[3];
    float phi = g_xmean * 0.1f;
    float pc = cosf(phi), ps = sinf(phi);
    int m[11];
#pragma unroll
    for (int j = 0; j < 11; j++) m[j] = n ^ (1 << j);
    float pacc = 0.f, hacc = 0.f;
#pragma unroll
    for (int q = 0; q < 4; q++) {
        int d  = q * 256 + threadIdx.x;
        int i0 = (n * 2) * DD + d, i1 = i0 + DD;
        float a0r = inr[i0], a0i = ini[i0], a1r = inr[i1], a1i = ini[i1];
        float n0r = c00r*a0r - c00i*a0i + c01r*a1r - c01i*a1i;
        float n0i = c00r*a0i + c00i*a0r + c01r*a1i + c01i*a1r;
        float sr = 0.f, si = 0.f;
#pragma unroll
        for (int j = 0; j < 11; j++) {
            int b0 = (m[j] * 2) * DD + d, b1 = b0 + DD;
            float x0r = inr[b0], x0i = ini[b0], x1r = inr[b1], x1i = ini[b1];
            sr += c10r*x0r - c10i*x0i + c11r*x1r - c11i*x1i;
            si += c10r*x0i + c10i*x0r + c11r*x1i + c11i*x1r;
        }
        float n1r = sr * (1.f/11.f), n1i = si * (1.f/11.f);
        float o0r = n0r*pc - n0i*ps, o0i = n0r*ps + n0i*pc;
        float o1r = n1r*pc - n1i*ps, o1i = n1r*ps + n1i*pc;
        outr[i0] = o0r;  outi[i0] = o0i;
        outr[i1] = o1r;  outi[i1] = o1i;
        pacc += o0r*o0r + o0i*o0i + o1r*o1r + o1i*o1i;
        hacc += atan2f(o0i + o1i, o0r + o1r);
    }
    rp[threadIdx.x] = pacc; rh[threadIdx.x] = hacc; __syncthreads();
    for (int st = 128; st > 0; st >>= 1) {
        if (threadIdx.x < st) { rp[threadIdx.x] += rp[threadIdx.x+st]; rh[threadIdx.x] += rh[threadIdx.x+st]; }
        __syncthreads();
    }
    if (threadIdx.x == 0) { g_probs[n] = rp[0]; g_ph[n] = rh[0] * (1.f/1024.f); }
}

__global__ void k_ptot() {
    __shared__ float red[1024];
    int t = threadIdx.x;
    red[t] = g_probs[t] + g_probs[t + 1024];
    __syncthreads();
    for (int st = 512; st > 0; st >>= 1) {
        if (t < st) red[t] += red[t + st];
        __syncthreads();
    }
    if (t == 0) g_ptot = red[0];
}

__global__ void k_inject(const float* __restrict__ src, float* __restrict__ dst) {
    int i = blockIdx.x, d = threadIdx.x;      // 512 threads
    float inv = 1.f / (g_ptot + 1e-8f);
    float p = g_probs[i] * inv;
    float interf = 0.f;
#pragma unroll
    for (int k = 0; k < 6; k++) interf += p - g_probs[i ^ (1 << k)] * inv;
    interf *= 0.03f;
    float phc = g_ph[i] * 0.3f;
    float c = cosf(phc), s = sinf(phc);
    float scale = 0.8f + 0.4f * p;
    float t1 = src[i*DD + d]       * scale;
    float t2 = src[i*DD + HD2 + d] * scale;
    dst[i*DD + d]       = 0.5f*(t1*c - t2*s) + 0.5f*t1 + interf;
    dst[i*DD + HD2 + d] = 0.5f*(t1*s + t2*c) + 0.5f*t2 + interf;
}

// smem-resident per-column frustration recurrence; 8 blocks x 128 columns
__global__ void k_frust(const float* __restrict__ fs) {
    extern __shared__ float fsm[];                 // sc[128*128] + sfs[1024]
    float* sc  = fsm;
    float* sfs = fsm + 128*128;
    int t = threadIdx.x;
    int col = blockIdx.x * 128 + t;
    for (int r = 0; r < 128; r++) sc[r*128 + t] = g_cells[r*DD + col];
    for (int i = t; i < 1024; i += 128) sfs[i] = fs[i];
    __syncthreads();
    float p0 = g_cells[128*DD + col];
    float p1 = g_cells[256*DD + col];
    float p2 = g_cells[512*DD + col];
    for (int i = 0; i < 128; i++) {
        float n0=0.f, n1=0.f, n2=0.f;
        if (i + 1 < 128) {
            n0 = g_cells[((i+1)^128)*DD + col];
            n1 = g_cells[((i+1)^256)*DD + col];
            n2 = g_cells[((i+1)^512)*DD + col];
        }
        float fi = sfs[i];
        float infl = fi*(sfs[i^128]*p0 + sfs[i^256]*p1 + sfs[i^512]*p2);
#pragma unroll
        for (int b = 0; b < 7; b++) {
            int j = i ^ (1 << b);
            infl += fi * sfs[j] * sc[j*128 + t];
        }
        sc[i*128 + t] = 0.85f * sc[i*128 + t] + 0.015f * infl;
        p0 = n0; p1 = n1; p2 = n2;
    }
    for (int r = 0; r < 128; r++) g_cells[r*DD + col] = sc[r*128 + t];
}

__global__ void k_wave(const int* __restrict__ step) {
    int i = blockIdx.x;
    float st  = (float)step[0];
    float fwd = fmodf(st * 0.15f, 2048.f);
    float bwd = fmodf(2048.f - st * 0.15f, 2048.f);
    float fi  = (float)i;
    float c1 = coshf((fi - fwd) * 0.5f), c2 = coshf((fi - bwd) * 0.5f);
    float amp = 1.f/(c1*c1) + 1.f/(c2*c2);
    float f = 1.f + 0.03f * amp;
#pragma unroll
    for (int q = 0; q < 4; q++) {
        int d = q * 256 + threadIdx.x;
        g_cells[i*DD + d] *= f;
    }
}

__global__ void k_morph(const int* __restrict__ step) {
    if (step[0] % 3 != 0) return;
    int col = blockIdx.x * 32 + threadIdx.x;
    float v[48];
    for (int k = 0; k < 48; k++) v[k] = g_cells[k*DD + col];
    for (int i = 0; i < 48; i++) {
        float s = 0.f;
        for (int k = 0; k < 48; k++) s += tanhf(v[k] - v[i]);
        v[i] = 0.9f * v[i] + 0.1f * s * (1.f/47.f);
    }
    for (int k = 0; k < 48; k++) g_cells[k*DD + col] = v[k];
}

__global__ void k_fmean() {
    int f = blockIdx.x;
    int col = blockIdx.y * 128 + threadIdx.x;
    float s = 0.f;
    for (int r = 0; r < 256; r++) s += g_cells[(f*256 + r)*DD + col];
    g_fmean[f*DD + col] = s * (1.f/256.f);
}

__global__ void k_faction(const int* __restrict__ step) {
    int n = blockIdx.x;
    int f = n >> 8, r = n & 255;
    bool debate = (step[0] > 5) && (r < 64);
#pragma unroll
    for (int q = 0; q < 4; q++) {
        int col = q * 256 + threadIdx.x;
        float v = 0.85f * g_cells[n*DD + col] + 0.15f * g_fmean[f*DD + col];
        if (debate) {
            float g = 0.f;
#pragma unroll
            for (int ff = 0; ff < 8; ff++) g += g_fmean[ff*DD + col];
            v = 0.85f * v + 0.15f * (g * 0.125f);
        }
        g_cells[n*DD + col] = v;
    }
}

__global__ void k_xproj(const float* __restrict__ x, const float* __restrict__ w,
                        const float* __restrict__ b) {
    int gw   = (blockIdx.x * blockDim.x + threadIdx.x) >> 5;
    int lane = threadIdx.x & 31;
    if (gw >= BB * DD) return;
    int bi = gw / DD, j = gw % DD;
    const float* xr = x + bi * INDIM;
    const float* wr = w + (size_t)j * INDIM;
    float s = 0.f;
    for (int k = lane; k < INDIM; k += 32) s += xr[k] * wr[k];
    for (int o = 16; o > 0; o >>= 1) s += __shfl_down_sync(0xffffffffu, s, o);
    if (lane == 0) g_xproj[gw] = s + b[j];
}

__global__ void k_bcast() {
    int row = blockIdx.x;
    int b = row / NC, n = row % NC;
#pragma unroll
    for (int q = 0; q < 4; q++) {
        int d = q * 256 + threadIdx.x;
        g_cellsB[(size_t)row*DD + d] = g_cells[n*DD + d] + 0.1f * g_xproj[b*DD + d];
    }
}

// ------------------------- tf32 tensor-core helpers ------------------------
__device__ __forceinline__ uint32_t f2tf32(float x) {
    uint32_t r; asm("cvt.rna.tf32.f32 %0, %1;" : "=r"(r) : "f"(x)); return r;
}
__device__ __forceinline__ void mma8(float* c, const uint32_t* a, const uint32_t* b) {
    asm volatile(
        "mma.sync.aligned.m16n8k8.row.col.f32.tf32.tf32.f32 "
        "{%0,%1,%2,%3},{%4,%5,%6,%7},{%8,%9},{%0,%1,%2,%3};"
        : "+f"(c[0]), "+f"(c[1]), "+f"(c[2]), "+f"(c[3])
        : "r"(a[0]), "r"(a[1]), "r"(a[2]), "r"(a[3]), "r"(b[0]), "r"(b[1]));
}
__device__ __forceinline__ void cpa16(float* dst, const float* src) {
    unsigned d = (unsigned)__cvta_generic_to_shared(dst);
    asm volatile("cp.async.cg.shared.global [%0], [%1], 16;\n" :: "r"(d), "l"(src));
}
__device__ __forceinline__ void cp_commit() { asm volatile("cp.async.commit_group;\n"); }
__device__ __forceinline__ void cp_wait0() { asm volatile("cp.async.wait_group 0;\n"); }

#define AST 40
#define NT_STAGE (128*AST*2)

#define LOAD_AFRAG(AS, AF, KC)                                            \
    _Pragma("unroll")                                                     \
    for (int mt = 0; mt < 4; mt++) {                                      \
        int rb = wm*64 + mt*16 + g;                                       \
        float2 lo = *(const float2*)&(AS)[rb*AST + (KC)];                 \
        float2 hi = *(const float2*)&(AS)[(rb+8)*AST + (KC)];             \
        (AF)[mt][0] = f2tf32(lo.x); (AF)[mt][2] = f2tf32(lo.y);           \
        (AF)[mt][1] = f2tf32(hi.x); (AF)[mt][3] = f2tf32(hi.y);           \
    }

// C[M,N] = alpha * A[M,K] @ W[N,K]^T (+bias). BM=BN=128, BK=32, 2-stage.
__global__ void __launch_bounds__(256, 2) tgemm_nt(
    const float* __restrict__ A, int lda,
    const float* __restrict__ W, int ldw,
    const float* __restrict__ bias,
    float* __restrict__ C, int ldc,
    int K, float alpha)
{
    extern __shared__ float sm[];
    int tid  = threadIdx.x;
    int wid  = tid >> 5, lane = tid & 31;
    int g = lane >> 2, t = lane & 3;
    int wm = wid & 1, wn = wid >> 1;

    int lr = tid >> 3;
    int lc = (tid & 7) << 2;
    const float* Ab = A + (size_t)(blockIdx.y*128 + lr)*lda + lc;
    const float* Wb = W + (size_t)(blockIdx.x*128 + lr)*ldw + lc;

    float acc[4][4][4] = {};
    int KT = K >> 5;

#define NT_LOAD(KT_)                                                      \
    {                                                                     \
        float* a_s = sm + ((KT_)&1)*NT_STAGE;                             \
        float* b_s = a_s + 128*AST;                                       \
        _Pragma("unroll")                                                 \
        for (int i = 0; i < 4; i++) {                                     \
            cpa16(&a_s[(lr + 32*i)*AST + lc], Ab + (size_t)(32*i)*lda + (KT_)*32); \
            cpa16(&b_s[(lr + 32*i)*AST + lc], Wb + (size_t)(32*i)*ldw + (KT_)*32); \
        }                                                                 \
        cp_commit();                                                      \
    }

    NT_LOAD(0);

    for (int kt = 0; kt < KT; kt++) {
        cp_wait0();
        __syncthreads();
        if (kt + 1 < KT) NT_LOAD(kt+1);
        const float* a_s = sm + (kt&1)*NT_STAGE;
        const float* b_s = a_s + 128*AST;
#pragma unroll
        for (int ks = 0; ks < 4; ks++) {
            uint32_t af[4][4], bf[4][2];
            int kc = ks*8 + 2*t;
            LOAD_AFRAG(a_s, af, kc)
#pragma unroll
            for (int nt = 0; nt < 4; nt++) {
                int nb = wn*32 + nt*8 + g;
                float2 bb = *(const float2*)&b_s[nb*AST + kc];
                bf[nt][0] = f2tf32(bb.x); bf[nt][1] = f2tf32(bb.y);
            }
#pragma unroll
            for (int mt = 0; mt < 4; mt++)
#pragma unroll
                for (int nt = 0; nt < 4; nt++)
                    mma8(acc[mt][nt], af[mt], bf[nt]);
        }
    }

    int row0 = blockIdx.y*128 + wm*64 + g;
    int col0 = blockIdx.x*128 + wn*32 + 2*t;
#pragma unroll
    for (int nt = 0; nt < 4; nt++) {
        int c = col0 + nt*8;
        float2 bv = make_float2(0.f, 0.f);
        if (bias) bv = *(const float2*)&bias[c];
#pragma unroll
        for (int mt = 0; mt < 4; mt++) {
            int r = row0 + mt*16;
            float2 o0, o1;
            o0.x = alpha*acc[mt][nt][0] + bv.x;  o0.y = alpha*acc[mt][nt][1] + bv.y;
            o1.x = alpha*acc[mt][nt][2] + bv.x;  o1.y = alpha*acc[mt][nt][3] + bv.y;
            *(float2*)&C[(size_t)r*ldc + c]     = o0;
            *(float2*)&C[(size_t)(r+8)*ldc + c] = o1;
        }
    }
}

// ---------------- fused attention: S=QK^T, e=exp, Z, O=eV ------------------
// Grid: (NC/64, BB*HH). CTA: 256 thr. Writes raw e -> g_scores, Z -> g_rowsum,
// O/Z -> g_av. No max subtraction (scores bounded ~|6|; softmax invariant).
#define QST 136   // sQ/sK row stride
#define VST 132   // sV row stride (k-major)
#define EST 68    // sE row stride

__global__ void __launch_bounds__(256, 1) k_fattn(
    const float* __restrict__ QKV, float* __restrict__ E,
    float* __restrict__ ZS, float* __restrict__ O)
{
    extern __shared__ float sm[];
    float* sQ = sm;                    // 64 x QST
    float* sK = sQ + 64*QST;           // 2 x 64 x QST
    float* sV = sK + 2*64*QST;         // 2 x 64 x VST
    float* sE = sV + 2*64*VST;         // 64 x EST
    float* sZ = sE + 64*EST;           // 64

    int qt = blockIdx.x, bh = blockIdx.y;
    int b = bh >> 3, h = bh & 7;
    int tid = threadIdx.x, lane = tid & 31, wid = tid >> 5;
    int g = lane >> 2, t = lane & 3;
    int wq = wid & 3, wk = wid >> 2;          // 4 q-groups x 2 k/d-groups

    const float* Qg = QKV + (size_t)(b*NC + qt*64)*D3 + h*128;
    const float* Kg = QKV + (size_t)b*NC*D3 + h*128 + 1024;
    const float* Vg = QKV + (size_t)b*NC*D3 + h*128 + 2048;

    // load Q (scaled by 1/sqrt(128)), init sZ
    {
        int r = tid >> 2, c4 = (tid & 3) * 32;   // 4 threads/row, 8 float4 each
        const float* qr = Qg + (size_t)r*D3 + c4;
        float* dst = sQ + r*QST + c4;
#pragma unroll
        for (int j = 0; j < 8; j++) {
            float4 v = *(const float4*)(qr + j*4);
            const float sc = 0.08838834764831845f;
            v.x*=sc; v.y*=sc; v.z*=sc; v.w*=sc;
            *(float4*)(dst + j*4) = v;
        }
        if (tid < 64) sZ[tid] = 0.f;
    }

#define KV_LOAD(KT_)                                                        \
    {                                                                       \
        float* k_s = sK + ((KT_)&1)*64*QST;                                 \
        float* v_s = sV + ((KT_)&1)*64*VST;                                 \
        int r = tid >> 2, c4 = (tid & 3) * 32;                              \
        const float* kr = Kg + (size_t)((KT_)*64 + r)*D3 + c4;              \
        const float* vr = Vg + (size_t)((KT_)*64 + r)*D3 + c4;              \
        _Pragma("unroll")                                                   \
        for (int j = 0; j < 8; j++) {                                       \
            cpa16(k_s + r*QST + c4 + j*4, kr + j*4);                        \
            cpa16(v_s + r*VST + c4 + j*4, vr + j*4);                        \
        }                                                                   \
        cp_commit();                                                        \
    }

    KV_LOAD(0);

    float oacc[8][4] = {};
    size_t ebase = (size_t)bh*NC*NC + (size_t)(qt*64)*NC;

    for (int kt = 0; kt < 32; kt++) {
        cp_wait0();
        __syncthreads();                       // KV(kt) ready; sE(kt-1) consumed
        if (kt + 1 < 32) KV_LOAD(kt+1);
        const float* k_s = sK + (kt&1)*64*QST;
        const float* v_s = sV + (kt&1)*64*VST;

        // ---- S = Q . K^T : warp tile 16(q) x 32(kl), k=128 ----
        float acc[4][4] = {};
#pragma unroll
        for (int kc8 = 0; kc8 < 16; kc8++) {
            int kc = kc8*8 + 2*t;
            uint32_t af[4], bf[4][2];
            {
                int rb = wq*16 + g;
                float2 lo = *(const float2*)&sQ[rb*QST + kc];
                float2 hi = *(const float2*)&sQ[(rb+8)*QST + kc];
                af[0] = f2tf32(lo.x); af[2] = f2tf32(lo.y);
                af[1] = f2tf32(hi.x); af[3] = f2tf32(hi.y);
            }
#pragma unroll
            for (int nt = 0; nt < 4; nt++) {
                int nb = wk*32 + nt*8 + g;
                float2 bb = *(const float2*)&k_s[nb*QST + kc];
                bf[nt][0] = f2tf32(bb.x); bf[nt][1] = f2tf32(bb.y);
            }
#pragma unroll
            for (int nt = 0; nt < 4; nt++) mma8(acc[nt], af, bf[nt]);
        }

        // exp + write sE + Z partials
        float z0 = 0.f, z1 = 0.f;
        int r0 = wq*16 + g;
        int c0 = wk*32 + 2*t;
#pragma unroll
        for (int nt = 0; nt < 4; nt++) {
            float e0 = __expf(acc[nt][0]);
            float e1 = __expf(acc[nt][1]);
            float e2 = __expf(acc[nt][2]);
            float e3 = __expf(acc[nt][3]);
            int c = c0 + nt*8;
            sE[r0*EST + c]       = e0;
            sE[r0*EST + c + 1]   = e1;
            sE[(r0+8)*EST + c]   = e2;
            sE[(r0+8)*EST + c+1] = e3;
            z0 += e0 + e1; z1 += e2 + e3;
        }
        // combine 4 lanes (t) owning same rows
        z0 += __shfl_xor_sync(0xffffffffu, z0, 1);
        z0 += __shfl_xor_sync(0xffffffffu, z0, 2);
        z1 += __shfl_xor_sync(0xffffffffu, z1, 1);
        z1 += __shfl_xor_sync(0xffffffffu, z1, 2);
        if (t == 0) {
            atomicAdd(&sZ[r0], z0);
            atomicAdd(&sZ[r0+8], z1);
        }
        __syncthreads();                       // sE complete

        // copy e tile to global (coalesced)
        {
            int r = tid >> 2, c4 = (tid & 3) * 16;
            float* dst = E + ebase + (size_t)r*NC + kt*64 + c4;
            const float* src = sE + r*EST + c4;
#pragma unroll
            for (int j = 0; j < 4; j++)
                *(float4*)(dst + j*4) = *(const float4*)(src + j*4);
        }

        // ---- O += e . V : warp tile 16(q) x 64(d), k=64 ----
#pragma unroll
        for (int kc8 = 0; kc8 < 8; kc8++) {
            int kc = kc8*8 + 2*t;
            uint32_t af[4], bf[8][2];
            {
                int rb = wq*16 + g;
                float2 lo = *(const float2*)&sE[rb*EST + kc];
                float2 hi = *(const float2*)&sE[(rb+8)*EST + kc];
                af[0] = f2tf32(lo.x); af[2] = f2tf32(lo.y);
                af[1] = f2tf32(hi.x); af[3] = f2tf32(hi.y);
            }
#pragma unroll
            for (int nt = 0; nt < 8; nt++) {
                int nb = wk*64 + nt*8 + g;
                bf[nt][0] = f2tf32(v_s[kc*VST + nb]);
                bf[nt][1] = f2tf32(v_s[(kc+1)*VST + nb]);
            }
#pragma unroll
            for (int nt = 0; nt < 8; nt++) mma8(oacc[nt], af, bf[nt]);
        }
    }
    __syncthreads();                           // sZ final

    // rowsums + normalized O
    if (tid < 64) ZS[bh*NC + qt*64 + tid] = sZ[tid];
    {
        int r0 = wq*16 + g;
        float zi0 = 1.f / sZ[r0];
        float zi1 = 1.f / sZ[r0 + 8];
        int qg0 = qt*64 + r0;
        int dc0 = h*128 + wk*64 + 2*t;
#pragma unroll
        for (int nt = 0; nt < 8; nt++) {
            int dc = dc0 + nt*8;
            *(float2*)&O[(size_t)(b*NC + qg0)*DD + dc] =
                make_float2(oacc[nt][0]*zi0, oacc[nt][1]*zi0);
            *(float2*)&O[(size_t)(b*NC + qg0 + 8)*DD + dc] =
                make_float2(oacc[nt][2]*zi1, oacc[nt][3]*zi1);
        }
    }
}

// --------------------- tension partials from raw e + Z --------------------
__global__ void __launch_bounds__(256) k_tens(const float* __restrict__ E) {
    __shared__ float r1[256], r2[256];
    __shared__ float zinv[8];
    int q = blockIdx.x, b = blockIdx.y;
    int tid = threadIdx.x;
    if (tid < 8) zinv[tid] = 0.125f / g_rowsum[(b*8 + tid)*NC + q];
    __syncthreads();
    const float* base = E + (size_t)b*8*NC*NC + (size_t)q*NC;
    const float mu0 = 1.f / 2048.f;
    float s1 = 0.f, s2 = 0.f;
    for (int k = tid; k < 2048; k += 256) {
        float m = 0.f;
#pragma unroll
        for (int h = 0; h < 8; h++) m += base[(size_t)h*NC*NC + k] * zinv[h];
        s1 += m;
        float d = m - mu0;
        s2 += d * d;
    }
    r1[tid] = s1; r2[tid] = s2; __syncthreads();
    for (int st = 128; st > 0; st >>= 1) {
        if (tid < st) { r1[tid] += r1[tid+st]; r2[tid] += r2[tid+st]; }
        __syncthreads();
    }
    if (tid == 0) { int bq = b*2048 + q; g_part1[bq] = r1[0]; g_part2[bq] = r2[0]; }
}

__global__ void k_tred() {
    __shared__ float r1[1024], r2[1024];
    int t = threadIdx.x;
    float s1 = 0.f, s2 = 0.f;
    for (int i = t; i < BB*NC; i += 1024) { s1 += g_part1[i]; s2 += g_part2[i]; }
    r1[t] = s1; r2[t] = s2; __syncthreads();
    for (int st = 512; st > 0; st >>= 1) {
        if (t < st) { r1[t] += r1[t+st]; r2[t] += r2[t+st]; }
        __syncthreads();
    }
    if (t == 0) {
        double Ne = 8388608.0;
        double S1 = (double)r1[0], D2 = (double)r2[0];
        double mu0 = 1.0 / 2048.0;
        double mu  = S1 / Ne;
        double var = (D2 - Ne * (mu - mu0) * (mu - mu0)) / (Ne - 1.0);
        if (var < 0.0) var = 0.0;
        g_tension += (float)sqrt(var);
    }
}

__global__ void k_addln(const float* __restrict__ g, const float* __restrict__ bta) {
    __shared__ float red[256];
    size_t row = blockIdx.x;
    int t = threadIdx.x;
    float v[4];
    float s = 0.f;
#pragma unroll
    for (int q = 0; q < 4; q++) {
        int d = q * 256 + t;
        v[q] = g_cellsB[row*DD + d] + g_tmp[row*DD + d];
        s += v[q];
    }
    red[t] = s; __syncthreads();
    for (int st = 128; st > 0; st >>= 1) {
        if (t < st) red[t] += red[t + st];
        __syncthreads();
    }
    float mu = red[0] * (1.f/1024.f);
    __syncthreads();
    float s2 = 0.f;
#pragma unroll
    for (int q = 0; q < 4; q++) { float d = v[q] - mu; s2 += d * d; }
    red[t] = s2; __syncthreads();
    for (int st = 128; st > 0; st >>= 1) {
        if (t < st) red[t] += red[t + st];
        __syncthreads();
    }
    float var  = red[0] * (1.f/1024.f);
    float rstd = rsqrtf(var + 1e-5f);
#pragma unroll
    for (int q = 0; q < 4; q++) {
        int d = q * 256 + t;
        g_cellsB[row*DD + d] = (v[q] - mu) * rstd * g[d] + bta[d];
    }
}

__global__ void k_twrite(float* __restrict__ out) { out[0] = g_tension * 0.5f; }

// ------------------------------- host launch -------------------------------
extern "C" void kernel_launch(void* const* d_in, const int* in_sizes, int n_in,
                              void* d_out, int out_size) {
    const float* x           = (const float*)d_in[0];
    const float* amp_real    = (const float*)d_in[1];
    const float* amp_imag    = (const float*)d_in[2];
    const float* coin_real   = (const float*)d_in[3];
    const float* coin_imag   = (const float*)d_in[4];
    const float* cell_emb    = (const float*)d_in[5];
    const float* fsigns      = (const float*)d_in[6];
    const float* w_in        = (const float*)d_in[7];
    const float* b_in        = (const float*)d_in[8];
    const float* attn_in_w   = (const float*)d_in[9];
    const float* attn_in_b   = (const float*)d_in[10];
    const float* attn_out_w  = (const float*)d_in[11];
    const float* attn_out_b  = (const float*)d_in[12];
    const float* ln_g        = (const float*)d_in[13];
    const float* ln_b        = (const float*)d_in[14];
    const float* w_out       = (const float*)d_in[15];
    const float* b_out       = (const float*)d_in[16];
    const int*   step        = (const int*)d_in[17];
    float* out = (float*)d_out;

    float *p_ar0, *p_ai0, *p_ar1, *p_ai1, *p_cells, *p_cellsB, *p_qkv, *p_scores,
          *p_av, *p_tmp, *p_rowsum;
    cudaGetSymbolAddress((void**)&p_ar0,    g_ampr0);
    cudaGetSymbolAddress((void**)&p_ai0,    g_ampi0);
    cudaGetSymbolAddress((void**)&p_ar1,    g_ampr1);
    cudaGetSymbolAddress((void**)&p_ai1,    g_ampi1);
    cudaGetSymbolAddress((void**)&p_cells,  g_cells);
    cudaGetSymbolAddress((void**)&p_cellsB, g_cellsB);
    cudaGetSymbolAddress((void**)&p_qkv,    g_qkv);
    cudaGetSymbolAddress((void**)&p_scores, g_scores);
    cudaGetSymbolAddress((void**)&p_av,     g_av);
    cudaGetSymbolAddress((void**)&p_tmp,    g_tmp);
    cudaGetSymbolAddress((void**)&p_rowsum, g_rowsum);

    const int nt_smem = NT_STAGE*2*(int)sizeof(float);  // 81920
    const int fa_smem = (64*QST + 2*64*QST + 2*64*VST + 64*EST + 64 + 16)*(int)sizeof(float);
    const int fr_smem = (128*128 + 1024)*(int)sizeof(float); // 69632
    static int attr_done = 0;
    if (!attr_done) {
        cudaFuncSetAttribute(tgemm_nt, cudaFuncAttributeMaxDynamicSharedMemorySize, nt_smem);
        cudaFuncSetAttribute(k_fattn,  cudaFuncAttributeMaxDynamicSharedMemorySize, fa_smem);
        cudaFuncSetAttribute(k_frust,  cudaFuncAttributeMaxDynamicSharedMemorySize, fr_smem);
        attr_done = 1;
    }

    // ---- update_cells preamble ----
    k_xmean<<<1, 256>>>(x, BB * INDIM);

    k_walkp<<<NC, 256>>>(amp_real, amp_imag, p_ar0, p_ai0, coin_real, coin_imag);
    k_ptot<<<1, 1024>>>();
    k_inject<<<NC, 512>>>(cell_emb, p_cells);
    k_walkp<<<NC, 256>>>(p_ar0, p_ai0, p_ar1, p_ai1, coin_real, coin_imag);
    k_ptot<<<1, 1024>>>();
    k_inject<<<NC, 512>>>(p_cells, p_cells);

    k_frust<<<8, 128, fr_smem>>>(fsigns);
    k_wave<<<NC, 256>>>(step);
    k_morph<<<32, 32>>>(step);
    k_fmean<<<dim3(8, 8), 128>>>();
    k_faction<<<NC, 256>>>(step);

    // ---- transformer body ----
    k_xproj<<<256, 256>>>(x, w_in, b_in);
    k_bcast<<<BB*NC, 256>>>();

    for (int l = 0; l < 2; l++) {
        // qkv = cellsB @ Wqkv^T + b : [4096,3072] K=1024
        tgemm_nt<<<dim3(24, 32, 1), 256, nt_smem>>>(
            p_cellsB, DD,
            attn_in_w + (size_t)l*D3*DD, DD,
            attn_in_b + (size_t)l*D3,
            p_qkv, D3, DD, 1.f);

        // fused attention: e, Z, O
        k_fattn<<<dim3(NC/64, BB*HH), 256, fa_smem>>>(p_qkv, p_scores, p_rowsum, p_av);

        // tension
        k_tens<<<dim3(NC, BB), 256>>>(p_scores);
        k_tred<<<1, 1024>>>();

        // out-proj : [4096,1024] K=1024
        tgemm_nt<<<dim3(8, 32, 1), 256, nt_smem>>>(
            p_av, DD,
            attn_out_w + (size_t)l*DD*DD, DD,
            attn_out_b + (size_t)l*DD,
            p_tmp, DD, DD, 1.f);

        k_addln<<<BB*NC, 256>>>(ln_g + (size_t)l*DD, ln_b + (size_t)l*DD);
    }

    // final projection: [4096,512] K=1024 -> d_out
    tgemm_nt<<<dim3(4, 32, 1), 256, nt_smem>>>(
        p_cellsB, DD,
        w_out, DD,
        b_out,
        out, INDIM, DD, 1.f);

    if (out_size >= BB*NC*INDIM + 1) {
        k_twrite<<<1, 1>>>(out + (size_t)BB*NC*INDIM);
    }
}

// round 6
// speedup vs baseline: 1.5546x; 1.5546x over previous
#include <cuda_runtime.h>
#include <math.h>
#include <stdint.h>

#define NC    2048
#define DD    1024
#define HD2   512
#define BB    2
#define HH    8
#define HDIM  128
#define D3    3072
#define INDIM 512

// ----------------------------- device scratch -----------------------------
__device__ float g_ampr0[NC*2*DD];
__device__ float g_ampi0[NC*2*DD];
__device__ float g_ampr1[NC*2*DD];
__device__ float g_ampi1[NC*2*DD];
__device__ float g_probs[NC];
__device__ float g_ph[NC];
__device__ float g_cells[NC*DD];
__device__ float g_fmean[8*DD];
__device__ float g_xproj[BB*DD];
__device__ float g_cellsB[BB*NC*DD];
__device__ float g_qkv[(size_t)BB*NC*D3];
__device__ float g_scores[(size_t)BB*HH*NC*NC];   // 256 MiB
__device__ float g_av[(size_t)BB*NC*DD];
__device__ float g_tmp[(size_t)BB*NC*DD];
__device__ float g_part1[BB*NC];
__device__ float g_part2[BB*NC];
__device__ float g_wqkv[2*D3*DD];     // tf32-rounded attn_in_w
__device__ float g_wout[2*DD*DD];     // tf32-rounded attn_out_w
__device__ float g_wfin[INDIM*DD];    // tf32-rounded w_out
__device__ float g_xmean;
__device__ float g_ptot;
__device__ float g_tension;

// ----------------------------- small kernels ------------------------------
__global__ void k_xmean(const float* __restrict__ x, int n) {
    __shared__ float red[256];
    float s = 0.f;
    for (int i = threadIdx.x; i < n; i += 256) s += x[i];
    red[threadIdx.x] = s; __syncthreads();
    for (int st = 128; st > 0; st >>= 1) {
        if (threadIdx.x < st) red[threadIdx.x] += red[threadIdx.x + st];
        __syncthreads();
    }
    if (threadIdx.x == 0) { g_xmean = red[0] / (float)n; g_tension = 0.f; }
}

__device__ __forceinline__ uint32_t f2tf32(float x) {
    uint32_t r; asm("cvt.rna.tf32.f32 %0, %1;" : "=r"(r) : "f"(x)); return r;
}
__device__ __forceinline__ float tfr(float x) { return __uint_as_float(f2tf32(x)); }

// round-copy weights to tf32 (idempotent w.r.t. in-GEMM cvt)
__global__ void k_roundcpy(float* __restrict__ dst, const float* __restrict__ src, int n4) {
    int i = blockIdx.x * 256 + threadIdx.x;
    if (i < n4) {
        float4 v = ((const float4*)src)[i];
        v.x = tfr(v.x); v.y = tfr(v.y); v.z = tfr(v.z); v.w = tfr(v.w);
        ((float4*)dst)[i] = v;
    }
}

// fused quantum-walk step + probs/phase reduction (norm skipped: scale-inv)
__global__ void k_walkp(const float* __restrict__ inr, const float* __restrict__ ini,
                        float* __restrict__ outr, float* __restrict__ outi,
                        const float* __restrict__ cr, const float* __restrict__ ci) {
    __shared__ float rp[256], rh[256];
    int n = blockIdx.x;
    float c00r=cr[0], c01r=cr[1], c10r=cr[2], c11r=cr[3];
    float c00i=ci[0], c01i=ci[1], c10i=ci[2], c11i=ci[3];
    float phi = g_xmean * 0.1f;
    float pc = cosf(phi), ps = sinf(phi);
    int m[11];
#pragma unroll
    for (int j = 0; j < 11; j++) m[j] = n ^ (1 << j);
    float pacc = 0.f, hacc = 0.f;
#pragma unroll
    for (int q = 0; q < 4; q++) {
        int d  = q * 256 + threadIdx.x;
        int i0 = (n * 2) * DD + d, i1 = i0 + DD;
        float a0r = inr[i0], a0i = ini[i0], a1r = inr[i1], a1i = ini[i1];
        float n0r = c00r*a0r - c00i*a0i + c01r*a1r - c01i*a1i;
        float n0i = c00r*a0i + c00i*a0r + c01r*a1i + c01i*a1r;
        float sr = 0.f, si = 0.f;
#pragma unroll
        for (int j = 0; j < 11; j++) {
            int b0 = (m[j] * 2) * DD + d, b1 = b0 + DD;
            float x0r = inr[b0], x0i = ini[b0], x1r = inr[b1], x1i = ini[b1];
            sr += c10r*x0r - c10i*x0i + c11r*x1r - c11i*x1i;
            si += c10r*x0i + c10i*x0r + c11r*x1i + c11i*x1r;
        }
        float n1r = sr * (1.f/11.f), n1i = si * (1.f/11.f);
        float o0r = n0r*pc - n0i*ps, o0i = n0r*ps + n0i*pc;
        float o1r = n1r*pc - n1i*ps, o1i = n1r*ps + n1i*pc;
        outr[i0] = o0r;  outi[i0] = o0i;
        outr[i1] = o1r;  outi[i1] = o1i;
        pacc += o0r*o0r + o0i*o0i + o1r*o1r + o1i*o1i;
        hacc += atan2f(o0i + o1i, o0r + o1r);
    }
    rp[threadIdx.x] = pacc; rh[threadIdx.x] = hacc; __syncthreads();
    for (int st = 128; st > 0; st >>= 1) {
        if (threadIdx.x < st) { rp[threadIdx.x] += rp[threadIdx.x+st]; rh[threadIdx.x] += rh[threadIdx.x+st]; }
        __syncthreads();
    }
    if (threadIdx.x == 0) { g_probs[n] = rp[0]; g_ph[n] = rh[0] * (1.f/1024.f); }
}

__global__ void k_ptot() {
    __shared__ float red[1024];
    int t = threadIdx.x;
    red[t] = g_probs[t] + g_probs[t + 1024];
    __syncthreads();
    for (int st = 512; st > 0; st >>= 1) {
        if (t < st) red[t] += red[t + st];
        __syncthreads();
    }
    if (t == 0) g_ptot = red[0];
}

__global__ void k_inject(const float* __restrict__ src, float* __restrict__ dst) {
    int i = blockIdx.x, d = threadIdx.x;      // 512 threads
    float inv = 1.f / (g_ptot + 1e-8f);
    float p = g_probs[i] * inv;
    float interf = 0.f;
#pragma unroll
    for (int k = 0; k < 6; k++) interf += p - g_probs[i ^ (1 << k)] * inv;
    interf *= 0.03f;
    float phc = g_ph[i] * 0.3f;
    float c = cosf(phc), s = sinf(phc);
    float scale = 0.8f + 0.4f * p;
    float t1 = src[i*DD + d]       * scale;
    float t2 = src[i*DD + HD2 + d] * scale;
    dst[i*DD + d]       = 0.5f*(t1*c - t2*s) + 0.5f*t1 + interf;
    dst[i*DD + HD2 + d] = 0.5f*(t1*s + t2*c) + 0.5f*t2 + interf;
}

// smem-resident per-column frustration recurrence; 8 blocks x 128 columns
__global__ void k_frust(const float* __restrict__ fs) {
    extern __shared__ float fsm[];                 // sc[128*128] + sfs[1024]
    float* sc  = fsm;
    float* sfs = fsm + 128*128;
    int t = threadIdx.x;
    int col = blockIdx.x * 128 + t;
    for (int r = 0; r < 128; r++) sc[r*128 + t] = g_cells[r*DD + col];
    for (int i = t; i < 1024; i += 128) sfs[i] = fs[i];
    __syncthreads();
    float p0 = g_cells[128*DD + col];
    float p1 = g_cells[256*DD + col];
    float p2 = g_cells[512*DD + col];
    for (int i = 0; i < 128; i++) {
        float n0=0.f, n1=0.f, n2=0.f;
        if (i + 1 < 128) {
            n0 = g_cells[((i+1)^128)*DD + col];
            n1 = g_cells[((i+1)^256)*DD + col];
            n2 = g_cells[((i+1)^512)*DD + col];
        }
        float fi = sfs[i];
        float infl = fi*(sfs[i^128]*p0 + sfs[i^256]*p1 + sfs[i^512]*p2);
#pragma unroll
        for (int b = 0; b < 7; b++) {
            int j = i ^ (1 << b);
            infl += fi * sfs[j] * sc[j*128 + t];
        }
        sc[i*128 + t] = 0.85f * sc[i*128 + t] + 0.015f * infl;
        p0 = n0; p1 = n1; p2 = n2;
    }
    for (int r = 0; r < 128; r++) g_cells[r*DD + col] = sc[r*128 + t];
}

__global__ void k_wave(const int* __restrict__ step) {
    int i = blockIdx.x;
    float st  = (float)step[0];
    float fwd = fmodf(st * 0.15f, 2048.f);
    float bwd = fmodf(2048.f - st * 0.15f, 2048.f);
    float fi  = (float)i;
    float c1 = coshf((fi - fwd) * 0.5f), c2 = coshf((fi - bwd) * 0.5f);
    float amp = 1.f/(c1*c1) + 1.f/(c2*c2);
    float f = 1.f + 0.03f * amp;
#pragma unroll
    for (int q = 0; q < 4; q++) {
        int d = q * 256 + threadIdx.x;
        g_cells[i*DD + d] *= f;
    }
}

__global__ void k_morph(const int* __restrict__ step) {
    if (step[0] % 3 != 0) return;
    int col = blockIdx.x * 32 + threadIdx.x;
    float v[48];
    for (int k = 0; k < 48; k++) v[k] = g_cells[k*DD + col];
    for (int i = 0; i < 48; i++) {
        float s = 0.f;
        for (int k = 0; k < 48; k++) s += tanhf(v[k] - v[i]);
        v[i] = 0.9f * v[i] + 0.1f * s * (1.f/47.f);
    }
    for (int k = 0; k < 48; k++) g_cells[k*DD + col] = v[k];
}

__global__ void k_fmean() {
    int f = blockIdx.x;
    int col = blockIdx.y * 128 + threadIdx.x;
    float s = 0.f;
    for (int r = 0; r < 256; r++) s += g_cells[(f*256 + r)*DD + col];
    g_fmean[f*DD + col] = s * (1.f/256.f);
}

__global__ void k_faction(const int* __restrict__ step) {
    int n = blockIdx.x;
    int f = n >> 8, r = n & 255;
    bool debate = (step[0] > 5) && (r < 64);
#pragma unroll
    for (int q = 0; q < 4; q++) {
        int col = q * 256 + threadIdx.x;
        float v = 0.85f * g_cells[n*DD + col] + 0.15f * g_fmean[f*DD + col];
        if (debate) {
            float g = 0.f;
#pragma unroll
            for (int ff = 0; ff < 8; ff++) g += g_fmean[ff*DD + col];
            v = 0.85f * v + 0.15f * (g * 0.125f);
        }
        g_cells[n*DD + col] = v;
    }
}

__global__ void k_xproj(const float* __restrict__ x, const float* __restrict__ w,
                        const float* __restrict__ b) {
    int gw   = (blockIdx.x * blockDim.x + threadIdx.x) >> 5;
    int lane = threadIdx.x & 31;
    if (gw >= BB * DD) return;
    int bi = gw / DD, j = gw % DD;
    const float* xr = x + bi * INDIM;
    const float* wr = w + (size_t)j * INDIM;
    float s = 0.f;
    for (int k = lane; k < INDIM; k += 32) s += xr[k] * wr[k];
    for (int o = 16; o > 0; o >>= 1) s += __shfl_down_sync(0xffffffffu, s, o);
    if (lane == 0) g_xproj[gw] = s + b[j];
}

__global__ void k_bcast() {
    int row = blockIdx.x;
    int b = row / NC, n = row % NC;
#pragma unroll
    for (int q = 0; q < 4; q++) {
        int d = q * 256 + threadIdx.x;
        g_cellsB[(size_t)row*DD + d] = g_cells[n*DD + d] + 0.1f * g_xproj[b*DD + d];
    }
}

// ------------------------- tf32 tensor-core GEMMs -------------------------
__device__ __forceinline__ void mma8(float* c, const uint32_t* a, const uint32_t* b) {
    asm volatile(
        "mma.sync.aligned.m16n8k8.row.col.f32.tf32.tf32.f32 "
        "{%0,%1,%2,%3},{%4,%5,%6,%7},{%8,%9},{%0,%1,%2,%3};"
        : "+f"(c[0]), "+f"(c[1]), "+f"(c[2]), "+f"(c[3])
        : "r"(a[0]), "r"(a[1]), "r"(a[2]), "r"(a[3]), "r"(b[0]), "r"(b[1]));
}
__device__ __forceinline__ void cpa16(float* dst, const float* src) {
    unsigned d = (unsigned)__cvta_generic_to_shared(dst);
    asm volatile("cp.async.cg.shared.global [%0], [%1], 16;\n" :: "r"(d), "l"(src));
}
__device__ __forceinline__ void cp_commit() { asm volatile("cp.async.commit_group;\n"); }
__device__ __forceinline__ void cp_wait0() { asm volatile("cp.async.wait_group 0;\n"); }

template<bool DOC>
__device__ __forceinline__ uint32_t opnd(float x) {
    return DOC ? f2tf32(x) : __float_as_uint(x);
}

#define AST 40           // smem row stride (floats) for [row][k] tiles
#define BSTN 132         // smem row stride for [k][n] tiles (NN B)
#define NT_STAGE (128*AST*2)
#define NN_STAGE (128*AST + 32*BSTN)

#define LOAD_AFRAG(AS, AF, KC, DOC)                                       \
    _Pragma("unroll")                                                     \
    for (int mt = 0; mt < 4; mt++) {                                      \
        int rb = wm*64 + mt*16 + g;                                       \
        float2 lo = *(const float2*)&(AS)[rb*AST + (KC)];                 \
        float2 hi = *(const float2*)&(AS)[(rb+8)*AST + (KC)];             \
        (AF)[mt][0] = opnd<DOC>(lo.x); (AF)[mt][2] = opnd<DOC>(lo.y);     \
        (AF)[mt][1] = opnd<DOC>(hi.x); (AF)[mt][3] = opnd<DOC>(hi.y);     \
    }

// C[M,N] = alpha * A[M,K] @ W[N,K]^T (+bias), batched. BM=BN=128, BK=32,
// 2-stage cp.async, ONE sync per k-tile, 2 CTAs/SM. CA/CB: cvt A/B operands.
// RO: round output to tf32 (for GEMM-only consumers).
template<bool CA, bool CB, bool RO>
__global__ void __launch_bounds__(256, 2) tgemm_nt(
    const float* __restrict__ A, int lda, long soA, long siA,
    const float* __restrict__ W, int ldw, long soW, long siW,
    const float* __restrict__ bias,
    float* __restrict__ C, int ldc, long soC, long siC,
    int inner, int K, float alpha)
{
    extern __shared__ float sm[];
    int z = blockIdx.z;
    int zo = z / inner, zi = z - zo * inner;
    A += (size_t)zo*soA + (size_t)zi*siA;
    W += (size_t)zo*soW + (size_t)zi*siW;
    C += (size_t)zo*soC + (size_t)zi*siC;

    int tid  = threadIdx.x;
    int wid  = tid >> 5, lane = tid & 31;
    int g = lane >> 2, t = lane & 3;
    int wm = wid & 1, wn = wid >> 1;

    int lr = tid >> 3;
    int lc = (tid & 7) << 2;
    const float* Ab = A + (size_t)(blockIdx.y*128 + lr)*lda + lc;
    const float* Wb = W + (size_t)(blockIdx.x*128 + lr)*ldw + lc;

    float acc[4][4][4] = {};
    int KT = K >> 5;

#define NT_LOAD(KT_)                                                      \
    {                                                                     \
        float* a_s = sm + ((KT_)&1)*NT_STAGE;                             \
        float* b_s = a_s + 128*AST;                                       \
        _Pragma("unroll")                                                 \
        for (int i = 0; i < 4; i++) {                                     \
            cpa16(&a_s[(lr + 32*i)*AST + lc], Ab + (size_t)(32*i)*lda + (KT_)*32); \
            cpa16(&b_s[(lr + 32*i)*AST + lc], Wb + (size_t)(32*i)*ldw + (KT_)*32); \
        }                                                                 \
        cp_commit();                                                      \
    }

    NT_LOAD(0);

    for (int kt = 0; kt < KT; kt++) {
        cp_wait0();
        __syncthreads();
        if (kt + 1 < KT) NT_LOAD(kt+1);
        const float* a_s = sm + (kt&1)*NT_STAGE;
        const float* b_s = a_s + 128*AST;
#pragma unroll
        for (int ks = 0; ks < 4; ks++) {
            uint32_t af[4][4], bf[4][2];
            int kc = ks*8 + 2*t;
            LOAD_AFRAG(a_s, af, kc, CA)
#pragma unroll
            for (int nt = 0; nt < 4; nt++) {
                int nb = wn*32 + nt*8 + g;
                float2 bb = *(const float2*)&b_s[nb*AST + kc];
                bf[nt][0] = opnd<CB>(bb.x); bf[nt][1] = opnd<CB>(bb.y);
            }
#pragma unroll
            for (int mt = 0; mt < 4; mt++)
#pragma unroll
                for (int nt = 0; nt < 4; nt++)
                    mma8(acc[mt][nt], af[mt], bf[nt]);
        }
    }

    int row0 = blockIdx.y*128 + wm*64 + g;
    int col0 = blockIdx.x*128 + wn*32 + 2*t;
#pragma unroll
    for (int nt = 0; nt < 4; nt++) {
        int c = col0 + nt*8;
        float2 bv = make_float2(0.f, 0.f);
        if (bias) bv = *(const float2*)&bias[c];
#pragma unroll
        for (int mt = 0; mt < 4; mt++) {
            int r = row0 + mt*16;
            float2 o0, o1;
            o0.x = alpha*acc[mt][nt][0] + bv.x;  o0.y = alpha*acc[mt][nt][1] + bv.y;
            o1.x = alpha*acc[mt][nt][2] + bv.x;  o1.y = alpha*acc[mt][nt][3] + bv.y;
            if (RO) {
                o0.x = tfr(o0.x); o0.y = tfr(o0.y);
                o1.x = tfr(o1.x); o1.y = tfr(o1.y);
            }
            *(float2*)&C[(size_t)r*ldc + c]     = o0;
            *(float2*)&C[(size_t)(r+8)*ldc + c] = o1;
        }
    }
}

// C[M,N] = A[M,K] @ B[K,N], batched. BM=BN=128, BK=32, 2-stage, 1 sync/iter.
template<bool CA, bool CB, bool RO>
__global__ void __launch_bounds__(256, 2) tgemm_nn(
    const float* __restrict__ A, int lda, long soA, long siA,
    const float* __restrict__ Bm, int ldb, long soB, long siB,
    float* __restrict__ C, int ldc, long soC, long siC,
    int inner, int K)
{
    extern __shared__ float sm[];
    int z = blockIdx.z;
    int zo = z / inner, zi = z - zo * inner;
    A  += (size_t)zo*soA + (size_t)zi*siA;
    Bm += (size_t)zo*soB + (size_t)zi*siB;
    C  += (size_t)zo*soC + (size_t)zi*siC;

    int tid  = threadIdx.x;
    int wid  = tid >> 5, lane = tid & 31;
    int g = lane >> 2, t = lane & 3;
    int wm = wid & 1, wn = wid >> 1;

    int lr = tid >> 3;
    int lc = (tid & 7) << 2;
    const float* Ab = A + (size_t)(blockIdx.y*128 + lr)*lda + lc;
    int br = tid >> 5;
    int bc = (tid & 31) << 2;
    const float* Bb = Bm + blockIdx.x*128 + bc;

    float acc[4][4][4] = {};
    int KT = K >> 5;

#define NN_LOAD(KT_)                                                      \
    {                                                                     \
        float* a_s = sm + ((KT_)&1)*NN_STAGE;                             \
        float* b_s = a_s + 128*AST;                                       \
        _Pragma("unroll")                                                 \
        for (int i = 0; i < 4; i++) {                                     \
            cpa16(&a_s[(lr + 32*i)*AST + lc], Ab + (size_t)(32*i)*lda + (KT_)*32); \
            cpa16(&b_s[(br + 8*i)*BSTN + bc], Bb + (size_t)((KT_)*32 + br + 8*i)*ldb); \
        }                                                                 \
        cp_commit();                                                      \
    }

    NN_LOAD(0);

    for (int kt = 0; kt < KT; kt++) {
        cp_wait0();
        __syncthreads();
        if (kt + 1 < KT) NN_LOAD(kt+1);
        const float* a_s = sm + (kt&1)*NN_STAGE;
        const float* b_s = a_s + 128*AST;
#pragma unroll
        for (int ks = 0; ks < 4; ks++) {
            uint32_t af[4][4], bf[4][2];
            int kc = ks*8 + 2*t;
            LOAD_AFRAG(a_s, af, kc, CA)
#pragma unroll
            for (int nt = 0; nt < 4; nt++) {
                int nb = wn*32 + nt*8 + g;
                bf[nt][0] = opnd<CB>(b_s[kc*BSTN + nb]);
                bf[nt][1] = opnd<CB>(b_s[(kc+1)*BSTN + nb]);
            }
#pragma unroll
            for (int mt = 0; mt < 4; mt++)
#pragma unroll
                for (int nt = 0; nt < 4; nt++)
                    mma8(acc[mt][nt], af[mt], bf[nt]);
        }
    }

    int row0 = blockIdx.y*128 + wm*64 + g;
    int col0 = blockIdx.x*128 + wn*32 + 2*t;
#pragma unroll
    for (int nt = 0; nt < 4; nt++) {
        int c = col0 + nt*8;
#pragma unroll
        for (int mt = 0; mt < 4; mt++) {
            int r = row0 + mt*16;
            float o0 = acc[mt][nt][0], o1 = acc[mt][nt][1];
            float o2 = acc[mt][nt][2], o3 = acc[mt][nt][3];
            if (RO) { o0 = tfr(o0); o1 = tfr(o1); o2 = tfr(o2); o3 = tfr(o3); }
            *(float2*)&C[(size_t)r*ldc + c]     = make_float2(o0, o1);
            *(float2*)&C[(size_t)(r+8)*ldc + c] = make_float2(o2, o3);
        }
    }
}

// ------------------ fused softmax (8 heads) + tension partials ------------
// writes tf32-rounded probs (AV GEMM would round them anyway)
__global__ void __launch_bounds__(256) k_smaxt(float* __restrict__ S) {
    extern __shared__ float sp[];           // 8*2048 probs + 512 reduction
    float* red = sp + 8*2048;
    int q = blockIdx.x, b = blockIdx.y;
    int tid = threadIdx.x, h = tid >> 5, lane = tid & 31;
    float* row = S + (size_t)(b*8+h)*NC*NC + (size_t)q*NC;
    float4 v[16];
    float m = -1e30f;
#pragma unroll
    for (int i = 0; i < 16; i++) {
        v[i] = ((const float4*)row)[lane + 32*i];
        m = fmaxf(m, fmaxf(fmaxf(v[i].x, v[i].y), fmaxf(v[i].z, v[i].w)));
    }
#pragma unroll
    for (int o = 16; o > 0; o >>= 1) m = fmaxf(m, __shfl_xor_sync(0xffffffffu, m, o));
    float s = 0.f;
#pragma unroll
    for (int i = 0; i < 16; i++) {
        v[i].x = __expf(v[i].x - m); v[i].y = __expf(v[i].y - m);
        v[i].z = __expf(v[i].z - m); v[i].w = __expf(v[i].w - m);
        s += v[i].x + v[i].y + v[i].z + v[i].w;
    }
#pragma unroll
    for (int o = 16; o > 0; o >>= 1) s += __shfl_xor_sync(0xffffffffu, s, o);
    float inv = 1.f / s;
    float4* sph = (float4*)(sp + h*2048);
#pragma unroll
    for (int i = 0; i < 16; i++) {
        v[i].x = tfr(v[i].x * inv); v[i].y = tfr(v[i].y * inv);
        v[i].z = tfr(v[i].z * inv); v[i].w = tfr(v[i].w * inv);
        sph[lane + 32*i] = v[i];
        ((float4*)row)[lane + 32*i] = v[i];
    }
    __syncthreads();
    const float mu0 = 1.f / 2048.f;
    float s1 = 0.f, s2 = 0.f;
#pragma unroll
    for (int i = 0; i < 8; i++) {
        int k = tid + 256*i;
        float mm = 0.f;
#pragma unroll
        for (int hh = 0; hh < 8; hh++) mm += sp[hh*2048 + k];
        mm *= 0.125f;
        s1 += mm;
        float d = mm - mu0;
        s2 += d * d;
    }
    red[tid] = s1; red[256 + tid] = s2; __syncthreads();
    for (int st = 128; st > 0; st >>= 1) {
        if (tid < st) { red[tid] += red[tid+st]; red[256+tid] += red[256+tid+st]; }
        __syncthreads();
    }
    if (tid == 0) { int bq = b*2048 + q; g_part1[bq] = red[0]; g_part2[bq] = red[256]; }
}

__global__ void k_tred() {
    __shared__ float r1[1024], r2[1024];
    int t = threadIdx.x;
    float s1 = 0.f, s2 = 0.f;
    for (int i = t; i < BB*NC; i += 1024) { s1 += g_part1[i]; s2 += g_part2[i]; }
    r1[t] = s1; r2[t] = s2; __syncthreads();
    for (int st = 512; st > 0; st >>= 1) {
        if (t < st) { r1[t] += r1[t+st]; r2[t] += r2[t+st]; }
        __syncthreads();
    }
    if (t == 0) {
        double Ne = 8388608.0;
        double S1 = (double)r1[0], D2 = (double)r2[0];
        double mu0 = 1.0 / 2048.0;
        double mu  = S1 / Ne;
        double var = (D2 - Ne * (mu - mu0) * (mu - mu0)) / (Ne - 1.0);
        if (var < 0.0) var = 0.0;
        g_tension += (float)sqrt(var);
    }
}

__global__ void k_addln(const float* __restrict__ g, const float* __restrict__ bta) {
    __shared__ float red[256];
    size_t row = blockIdx.x;
    int t = threadIdx.x;
    float v[4];
    float s = 0.f;
#pragma unroll
    for (int q = 0; q < 4; q++) {
        int d = q * 256 + t;
        v[q] = g_cellsB[row*DD + d] + g_tmp[row*DD + d];
        s += v[q];
    }
    red[t] = s; __syncthreads();
    for (int st = 128; st > 0; st >>= 1) {
        if (t < st) red[t] += red[t + st];
        __syncthreads();
    }
    float mu = red[0] * (1.f/1024.f);
    __syncthreads();
    float s2 = 0.f;
#pragma unroll
    for (int q = 0; q < 4; q++) { float d = v[q] - mu; s2 += d * d; }
    red[t] = s2; __syncthreads();
    for (int st = 128; st > 0; st >>= 1) {
        if (t < st) red[t] += red[t + st];
        __syncthreads();
    }
    float var  = red[0] * (1.f/1024.f);
    float rstd = rsqrtf(var + 1e-5f);
#pragma unroll
    for (int q = 0; q < 4; q++) {
        int d = q * 256 + t;
        g_cellsB[row*DD + d] = (v[q] - mu) * rstd * g[d] + bta[d];
    }
}

__global__ void k_twrite(float* __restrict__ out) { out[0] = g_tension * 0.5f; }

// ------------------------------- host launch -------------------------------
extern "C" void kernel_launch(void* const* d_in, const int* in_sizes, int n_in,
                              void* d_out, int out_size) {
    const float* x           = (const float*)d_in[0];
    const float* amp_real    = (const float*)d_in[1];
    const float* amp_imag    = (const float*)d_in[2];
    const float* coin_real   = (const float*)d_in[3];
    const float* coin_imag   = (const float*)d_in[4];
    const float* cell_emb    = (const float*)d_in[5];
    const float* fsigns      = (const float*)d_in[6];
    const float* w_in        = (const float*)d_in[7];
    const float* b_in        = (const float*)d_in[8];
    const float* attn_in_w   = (const float*)d_in[9];
    const float* attn_in_b   = (const float*)d_in[10];
    const float* attn_out_w  = (const float*)d_in[11];
    const float* attn_out_b  = (const float*)d_in[12];
    const float* ln_g        = (const float*)d_in[13];
    const float* ln_b        = (const float*)d_in[14];
    const float* w_out       = (const float*)d_in[15];
    const float* b_out       = (const float*)d_in[16];
    const int*   step        = (const int*)d_in[17];
    float* out = (float*)d_out;

    float *p_ar0, *p_ai0, *p_ar1, *p_ai1, *p_cells, *p_cellsB, *p_qkv, *p_scores,
          *p_av, *p_tmp, *p_wqkv, *p_wout, *p_wfin;
    cudaGetSymbolAddress((void**)&p_ar0,    g_ampr0);
    cudaGetSymbolAddress((void**)&p_ai0,    g_ampi0);
    cudaGetSymbolAddress((void**)&p_ar1,    g_ampr1);
    cudaGetSymbolAddress((void**)&p_ai1,    g_ampi1);
    cudaGetSymbolAddress((void**)&p_cells,  g_cells);
    cudaGetSymbolAddress((void**)&p_cellsB, g_cellsB);
    cudaGetSymbolAddress((void**)&p_qkv,    g_qkv);
    cudaGetSymbolAddress((void**)&p_scores, g_scores);
    cudaGetSymbolAddress((void**)&p_av,     g_av);
    cudaGetSymbolAddress((void**)&p_tmp,    g_tmp);
    cudaGetSymbolAddress((void**)&p_wqkv,   g_wqkv);
    cudaGetSymbolAddress((void**)&p_wout,   g_wout);
    cudaGetSymbolAddress((void**)&p_wfin,   g_wfin);

    const int nt_smem = NT_STAGE*2*(int)sizeof(float);  // 81920
    const int nn_smem = NN_STAGE*2*(int)sizeof(float);  // 74752
    const int sx_smem = (8*2048 + 512)*(int)sizeof(float);  // 67584
    const int fr_smem = (128*128 + 1024)*(int)sizeof(float); // 69632
    static int attr_done = 0;
    if (!attr_done) {
        cudaFuncSetAttribute(tgemm_nt<true,false,true>,   cudaFuncAttributeMaxDynamicSharedMemorySize, nt_smem);
        cudaFuncSetAttribute(tgemm_nt<false,false,false>, cudaFuncAttributeMaxDynamicSharedMemorySize, nt_smem);
        cudaFuncSetAttribute(tgemm_nt<true,false,false>,  cudaFuncAttributeMaxDynamicSharedMemorySize, nt_smem);
        cudaFuncSetAttribute(tgemm_nn<false,false,true>,  cudaFuncAttributeMaxDynamicSharedMemorySize, nn_smem);
        cudaFuncSetAttribute(k_smaxt, cudaFuncAttributeMaxDynamicSharedMemorySize, sx_smem);
        cudaFuncSetAttribute(k_frust, cudaFuncAttributeMaxDynamicSharedMemorySize, fr_smem);
        attr_done = 1;
    }

    // ---- weight round-copy (tf32, idempotent vs in-GEMM cvt) ----
    {
        int n4a = 2*D3*DD/4, n4b = 2*DD*DD/4, n4c = INDIM*DD/4;
        k_roundcpy<<<(n4a+255)/256, 256>>>(p_wqkv, attn_in_w, n4a);
        k_roundcpy<<<(n4b+255)/256, 256>>>(p_wout, attn_out_w, n4b);
        k_roundcpy<<<(n4c+255)/256, 256>>>(p_wfin, w_out, n4c);
    }

    // ---- update_cells preamble ----
    k_xmean<<<1, 256>>>(x, BB * INDIM);

    k_walkp<<<NC, 256>>>(amp_real, amp_imag, p_ar0, p_ai0, coin_real, coin_imag);
    k_ptot<<<1, 1024>>>();
    k_inject<<<NC, 512>>>(cell_emb, p_cells);
    k_walkp<<<NC, 256>>>(p_ar0, p_ai0, p_ar1, p_ai1, coin_real, coin_imag);
    k_ptot<<<1, 1024>>>();
    k_inject<<<NC, 512>>>(p_cells, p_cells);

    k_frust<<<8, 128, fr_smem>>>(fsigns);
    k_wave<<<NC, 256>>>(step);
    k_morph<<<32, 32>>>(step);
    k_fmean<<<dim3(8, 8), 128>>>();
    k_faction<<<NC, 256>>>(step);

    // ---- transformer body ----
    k_xproj<<<256, 256>>>(x, w_in, b_in);
    k_bcast<<<BB*NC, 256>>>();

    const float inv_sqrt_hd = 0.0883883476483184f; // 1/sqrt(128)
    for (int l = 0; l < 2; l++) {
        // qkv = cellsB @ Wqkv^T + b : [4096,3072] K=1024; output tf32-rounded
        tgemm_nt<true,false,true><<<dim3(24, 32, 1), 256, nt_smem>>>(
            p_cellsB, DD, 0, 0,
            p_wqkv + (size_t)l*D3*DD, DD, 0, 0,
            attn_in_b + (size_t)l*D3,
            p_qkv, D3, 0, 0, 1, DD, 1.f);

        // scores: operands pre-rounded -> zero cvt in inner loop
        tgemm_nt<false,false,false><<<dim3(16, 16, 16), 256, nt_smem>>>(
            p_qkv,        D3, (long)NC*D3, 128,
            p_qkv + 1024, D3, (long)NC*D3, 128,
            nullptr,
            p_scores, NC, (long)8*NC*NC, (long)NC*NC,
            8, HDIM, inv_sqrt_hd);

        k_smaxt<<<dim3(NC, BB), 256, sx_smem>>>(p_scores);
        k_tred<<<1, 1024>>>();

        // av: probs + V pre-rounded -> zero cvt; output rounded for out-proj
        tgemm_nn<false,false,true><<<dim3(1, 16, 16), 256, nn_smem>>>(
            p_scores,     NC, (long)8*NC*NC, (long)NC*NC,
            p_qkv + 2048, D3, (long)NC*D3, 128,
            p_av, DD, (long)NC*DD, 128,
            8, NC);

        // out-proj: both operands pre-rounded; output exact (residual)
        tgemm_nt<false,false,false><<<dim3(8, 32, 1), 256, nt_smem>>>(
            p_av, DD, 0, 0,
            p_wout + (size_t)l*DD*DD, DD, 0, 0,
            attn_out_b + (size_t)l*DD,
            p_tmp, DD, 0, 0, 1, DD, 1.f);

        k_addln<<<BB*NC, 256>>>(ln_g + (size_t)l*DD, ln_b + (size_t)l*DD);
    }

    // final projection: [4096,512] K=1024 -> d_out (B pre-rounded)
    tgemm_nt<true,false,false><<<dim3(4, 32, 1), 256, nt_smem>>>(
        p_cellsB, DD, 0, 0,
        p_wfin, DD, 0, 0,
        b_out,
        out, INDIM, 0, 0, 1, DD, 1.f);

    if (out_size >= BB*NC*INDIM + 1) {
        k_twrite<<<1, 1>>>(out + (size_t)BB*NC*INDIM);
    }
}

// round 7
// speedup vs baseline: 1.5551x; 1.0003x over previous
#include <cuda_runtime.h>
#include <math.h>
#include <stdint.h>

#define NC    2048
#define DD    1024
#define HD2   512
#define BB    2
#define HH    8
#define HDIM  128
#define D3    3072
#define INDIM 512

// ----------------------------- device scratch -----------------------------
__device__ float g_ampr0[NC*2*DD];
__device__ float g_ampi0[NC*2*DD];
__device__ float g_ampr1[NC*2*DD];
__device__ float g_ampi1[NC*2*DD];
__device__ float g_probs[NC];
__device__ float g_ph[NC];
__device__ float g_cells[NC*DD];
__device__ float g_fmean[8*DD];
__device__ float g_xproj[BB*DD];
__device__ float g_cellsB[BB*NC*DD];
__device__ float g_qkv[(size_t)BB*NC*D3];
__device__ float g_scores[(size_t)BB*HH*NC*NC];   // raw exp(S), 256 MiB
__device__ float g_rowsum[BB*HH*NC];
__device__ float g_av[(size_t)BB*NC*DD];
__device__ float g_tmp[(size_t)BB*NC*DD];
__device__ float g_part1[BB*NC];
__device__ float g_part2[BB*NC];
__device__ float g_wqkv[2*D3*DD];     // tf32-rounded attn_in_w
__device__ float g_wout[2*DD*DD];     // tf32-rounded attn_out_w
__device__ float g_wfin[INDIM*DD];    // tf32-rounded w_out
__device__ float g_xmean;
__device__ float g_ptot;
__device__ float g_tension;

// ----------------------------- small kernels ------------------------------
__global__ void k_xmean(const float* __restrict__ x, int n) {
    __shared__ float red[256];
    float s = 0.f;
    for (int i = threadIdx.x; i < n; i += 256) s += x[i];
    red[threadIdx.x] = s; __syncthreads();
    for (int st = 128; st > 0; st >>= 1) {
        if (threadIdx.x < st) red[threadIdx.x] += red[threadIdx.x + st];
        __syncthreads();
    }
    if (threadIdx.x == 0) { g_xmean = red[0] / (float)n; g_tension = 0.f; }
}

__device__ __forceinline__ uint32_t f2tf32(float x) {
    uint32_t r; asm("cvt.rna.tf32.f32 %0, %1;" : "=r"(r) : "f"(x)); return r;
}
__device__ __forceinline__ float tfr(float x) { return __uint_as_float(f2tf32(x)); }

// round-copy weights to tf32 (idempotent w.r.t. in-GEMM cvt)
__global__ void k_roundcpy(float* __restrict__ dst, const float* __restrict__ src, int n4) {
    int i = blockIdx.x * 256 + threadIdx.x;
    if (i < n4) {
        float4 v = ((const float4*)src)[i];
        v.x = tfr(v.x); v.y = tfr(v.y); v.z = tfr(v.z); v.w = tfr(v.w);
        ((float4*)dst)[i] = v;
    }
}

// fused quantum-walk step + probs/phase reduction (norm skipped: scale-inv)
__global__ void k_walkp(const float* __restrict__ inr, const float* __restrict__ ini,
                        float* __restrict__ outr, float* __restrict__ outi,
                        const float* __restrict__ cr, const float* __restrict__ ci) {
    __shared__ float rp[256], rh[256];
    int n = blockIdx.x;
    float c00r=cr[0], c01r=cr[1], c10r=cr[2], c11r=cr[3];
    float c00i=ci[0], c01i=ci[1], c10i=ci[2], c11i=ci[3];
    float phi = g_xmean * 0.1f;
    float pc = cosf(phi), ps = sinf(phi);
    int m[11];
#pragma unroll
    for (int j = 0; j < 11; j++) m[j] = n ^ (1 << j);
    float pacc = 0.f, hacc = 0.f;
#pragma unroll
    for (int q = 0; q < 4; q++) {
        int d  = q * 256 + threadIdx.x;
        int i0 = (n * 2) * DD + d, i1 = i0 + DD;
        float a0r = inr[i0], a0i = ini[i0], a1r = inr[i1], a1i = ini[i1];
        float n0r = c00r*a0r - c00i*a0i + c01r*a1r - c01i*a1i;
        float n0i = c00r*a0i + c00i*a0r + c01r*a1i + c01i*a1r;
        float sr = 0.f, si = 0.f;
#pragma unroll
        for (int j = 0; j < 11; j++) {
            int b0 = (m[j] * 2) * DD + d, b1 = b0 + DD;
            float x0r = inr[b0], x0i = ini[b0], x1r = inr[b1], x1i = ini[b1];
            sr += c10r*x0r - c10i*x0i + c11r*x1r - c11i*x1i;
            si += c10r*x0i + c10i*x0r + c11r*x1i + c11i*x1r;
        }
        float n1r = sr * (1.f/11.f), n1i = si * (1.f/11.f);
        float o0r = n0r*pc - n0i*ps, o0i = n0r*ps + n0i*pc;
        float o1r = n1r*pc - n1i*ps, o1i = n1r*ps + n1i*pc;
        outr[i0] = o0r;  outi[i0] = o0i;
        outr[i1] = o1r;  outi[i1] = o1i;
        pacc += o0r*o0r + o0i*o0i + o1r*o1r + o1i*o1i;
        hacc += atan2f(o0i + o1i, o0r + o1r);
    }
    rp[threadIdx.x] = pacc; rh[threadIdx.x] = hacc; __syncthreads();
    for (int st = 128; st > 0; st >>= 1) {
        if (threadIdx.x < st) { rp[threadIdx.x] += rp[threadIdx.x+st]; rh[threadIdx.x] += rh[threadIdx.x+st]; }
        __syncthreads();
    }
    if (threadIdx.x == 0) { g_probs[n] = rp[0]; g_ph[n] = rh[0] * (1.f/1024.f); }
}

__global__ void k_ptot() {
    __shared__ float red[1024];
    int t = threadIdx.x;
    red[t] = g_probs[t] + g_probs[t + 1024];
    __syncthreads();
    for (int st = 512; st > 0; st >>= 1) {
        if (t < st) red[t] += red[t + st];
        __syncthreads();
    }
    if (t == 0) g_ptot = red[0];
}

__global__ void k_inject(const float* __restrict__ src, float* __restrict__ dst) {
    int i = blockIdx.x, d = threadIdx.x;      // 512 threads
    float inv = 1.f / (g_ptot + 1e-8f);
    float p = g_probs[i] * inv;
    float interf = 0.f;
#pragma unroll
    for (int k = 0; k < 6; k++) interf += p - g_probs[i ^ (1 << k)] * inv;
    interf *= 0.03f;
    float phc = g_ph[i] * 0.3f;
    float c = cosf(phc), s = sinf(phc);
    float scale = 0.8f + 0.4f * p;
    float t1 = src[i*DD + d]       * scale;
    float t2 = src[i*DD + HD2 + d] * scale;
    dst[i*DD + d]       = 0.5f*(t1*c - t2*s) + 0.5f*t1 + interf;
    dst[i*DD + HD2 + d] = 0.5f*(t1*s + t2*c) + 0.5f*t2 + interf;
}

// smem-resident per-column frustration recurrence; 8 blocks x 128 columns
__global__ void k_frust(const float* __restrict__ fs) {
    extern __shared__ float fsm[];                 // sc[128*128] + sfs[1024]
    float* sc  = fsm;
    float* sfs = fsm + 128*128;
    int t = threadIdx.x;
    int col = blockIdx.x * 128 + t;
    for (int r = 0; r < 128; r++) sc[r*128 + t] = g_cells[r*DD + col];
    for (int i = t; i < 1024; i += 128) sfs[i] = fs[i];
    __syncthreads();
    float p0 = g_cells[128*DD + col];
    float p1 = g_cells[256*DD + col];
    float p2 = g_cells[512*DD + col];
    for (int i = 0; i < 128; i++) {
        float n0=0.f, n1=0.f, n2=0.f;
        if (i + 1 < 128) {
            n0 = g_cells[((i+1)^128)*DD + col];
            n1 = g_cells[((i+1)^256)*DD + col];
            n2 = g_cells[((i+1)^512)*DD + col];
        }
        float fi = sfs[i];
        float infl = fi*(sfs[i^128]*p0 + sfs[i^256]*p1 + sfs[i^512]*p2);
#pragma unroll
        for (int b = 0; b < 7; b++) {
            int j = i ^ (1 << b);
            infl += fi * sfs[j] * sc[j*128 + t];
        }
        sc[i*128 + t] = 0.85f * sc[i*128 + t] + 0.015f * infl;
        p0 = n0; p1 = n1; p2 = n2;
    }
    for (int r = 0; r < 128; r++) g_cells[r*DD + col] = sc[r*128 + t];
}

__global__ void k_wave(const int* __restrict__ step) {
    int i = blockIdx.x;
    float st  = (float)step[0];
    float fwd = fmodf(st * 0.15f, 2048.f);
    float bwd = fmodf(2048.f - st * 0.15f, 2048.f);
    float fi  = (float)i;
    float c1 = coshf((fi - fwd) * 0.5f), c2 = coshf((fi - bwd) * 0.5f);
    float amp = 1.f/(c1*c1) + 1.f/(c2*c2);
    float f = 1.f + 0.03f * amp;
#pragma unroll
    for (int q = 0; q < 4; q++) {
        int d = q * 256 + threadIdx.x;
        g_cells[i*DD + d] *= f;
    }
}

__global__ void k_morph(const int* __restrict__ step) {
    if (step[0] % 3 != 0) return;
    int col = blockIdx.x * 32 + threadIdx.x;
    float v[48];
    for (int k = 0; k < 48; k++) v[k] = g_cells[k*DD + col];
    for (int i = 0; i < 48; i++) {
        float s = 0.f;
        for (int k = 0; k < 48; k++) s += tanhf(v[k] - v[i]);
        v[i] = 0.9f * v[i] + 0.1f * s * (1.f/47.f);
    }
    for (int k = 0; k < 48; k++) g_cells[k*DD + col] = v[k];
}

__global__ void k_fmean() {
    int f = blockIdx.x;
    int col = blockIdx.y * 128 + threadIdx.x;
    float s = 0.f;
    for (int r = 0; r < 256; r++) s += g_cells[(f*256 + r)*DD + col];
    g_fmean[f*DD + col] = s * (1.f/256.f);
}

__global__ void k_faction(const int* __restrict__ step) {
    int n = blockIdx.x;
    int f = n >> 8, r = n & 255;
    bool debate = (step[0] > 5) && (r < 64);
#pragma unroll
    for (int q = 0; q < 4; q++) {
        int col = q * 256 + threadIdx.x;
        float v = 0.85f * g_cells[n*DD + col] + 0.15f * g_fmean[f*DD + col];
        if (debate) {
            float g = 0.f;
#pragma unroll
            for (int ff = 0; ff < 8; ff++) g += g_fmean[ff*DD + col];
            v = 0.85f * v + 0.15f * (g * 0.125f);
        }
        g_cells[n*DD + col] = v;
    }
}

__global__ void k_xproj(const float* __restrict__ x, const float* __restrict__ w,
                        const float* __restrict__ b) {
    int gw   = (blockIdx.x * blockDim.x + threadIdx.x) >> 5;
    int lane = threadIdx.x & 31;
    if (gw >= BB * DD) return;
    int bi = gw / DD, j = gw % DD;
    const float* xr = x + bi * INDIM;
    const float* wr = w + (size_t)j * INDIM;
    float s = 0.f;
    for (int k = lane; k < INDIM; k += 32) s += xr[k] * wr[k];
    for (int o = 16; o > 0; o >>= 1) s += __shfl_down_sync(0xffffffffu, s, o);
    if (lane == 0) g_xproj[gw] = s + b[j];
}

__global__ void k_bcast() {
    int row = blockIdx.x;
    int b = row / NC, n = row % NC;
#pragma unroll
    for (int q = 0; q < 4; q++) {
        int d = q * 256 + threadIdx.x;
        g_cellsB[(size_t)row*DD + d] = g_cells[n*DD + d] + 0.1f * g_xproj[b*DD + d];
    }
}

// ------------------------- tf32 tensor-core GEMMs -------------------------
__device__ __forceinline__ void mma8(float* c, const uint32_t* a, const uint32_t* b) {
    asm volatile(
        "mma.sync.aligned.m16n8k8.row.col.f32.tf32.tf32.f32 "
        "{%0,%1,%2,%3},{%4,%5,%6,%7},{%8,%9},{%0,%1,%2,%3};"
        : "+f"(c[0]), "+f"(c[1]), "+f"(c[2]), "+f"(c[3])
        : "r"(a[0]), "r"(a[1]), "r"(a[2]), "r"(a[3]), "r"(b[0]), "r"(b[1]));
}
__device__ __forceinline__ void cpa16(float* dst, const float* src) {
    unsigned d = (unsigned)__cvta_generic_to_shared(dst);
    asm volatile("cp.async.cg.shared.global [%0], [%1], 16;\n" :: "r"(d), "l"(src));
}
__device__ __forceinline__ void cp_commit() { asm volatile("cp.async.commit_group;\n"); }
__device__ __forceinline__ void cp_wait0() { asm volatile("cp.async.wait_group 0;\n"); }

template<bool DOC>
__device__ __forceinline__ uint32_t opnd(float x) {
    return DOC ? f2tf32(x) : __float_as_uint(x);
}

#define AST 40           // smem row stride (floats) for [row][k] tiles
#define BSTN 132         // smem row stride for [k][n] tiles (NN B)
#define NT_STAGE (128*AST*2)
#define NN_STAGE (128*AST + 32*BSTN)

#define LOAD_AFRAG(AS, AF, KC, DOC)                                       \
    _Pragma("unroll")                                                     \
    for (int mt = 0; mt < 4; mt++) {                                      \
        int rb = wm*64 + mt*16 + g;                                       \
        float2 lo = *(const float2*)&(AS)[rb*AST + (KC)];                 \
        float2 hi = *(const float2*)&(AS)[(rb+8)*AST + (KC)];             \
        (AF)[mt][0] = opnd<DOC>(lo.x); (AF)[mt][2] = opnd<DOC>(lo.y);     \
        (AF)[mt][1] = opnd<DOC>(hi.x); (AF)[mt][3] = opnd<DOC>(hi.y);     \
    }

// C = alpha*A@W^T (+bias); EXPO: C = tf32(exp(alpha*acc)); RO: round output.
template<bool CA, bool CB, bool EXPO, bool RO>
__global__ void __launch_bounds__(256, 2) tgemm_nt(
    const float* __restrict__ A, int lda, long soA, long siA,
    const float* __restrict__ W, int ldw, long soW, long siW,
    const float* __restrict__ bias,
    float* __restrict__ C, int ldc, long soC, long siC,
    int inner, int K, float alpha)
{
    extern __shared__ float sm[];
    int z = blockIdx.z;
    int zo = z / inner, zi = z - zo * inner;
    A += (size_t)zo*soA + (size_t)zi*siA;
    W += (size_t)zo*soW + (size_t)zi*siW;
    C += (size_t)zo*soC + (size_t)zi*siC;

    int tid  = threadIdx.x;
    int wid  = tid >> 5, lane = tid & 31;
    int g = lane >> 2, t = lane & 3;
    int wm = wid & 1, wn = wid >> 1;

    int lr = tid >> 3;
    int lc = (tid & 7) << 2;
    const float* Ab = A + (size_t)(blockIdx.y*128 + lr)*lda + lc;
    const float* Wb = W + (size_t)(blockIdx.x*128 + lr)*ldw + lc;

    float acc[4][4][4] = {};
    int KT = K >> 5;

#define NT_LOAD(KT_)                                                      \
    {                                                                     \
        float* a_s = sm + ((KT_)&1)*NT_STAGE;                             \
        float* b_s = a_s + 128*AST;                                       \
        _Pragma("unroll")                                                 \
        for (int i = 0; i < 4; i++) {                                     \
            cpa16(&a_s[(lr + 32*i)*AST + lc], Ab + (size_t)(32*i)*lda + (KT_)*32); \
            cpa16(&b_s[(lr + 32*i)*AST + lc], Wb + (size_t)(32*i)*ldw + (KT_)*32); \
        }                                                                 \
        cp_commit();                                                      \
    }

    NT_LOAD(0);

    for (int kt = 0; kt < KT; kt++) {
        cp_wait0();
        __syncthreads();
        if (kt + 1 < KT) NT_LOAD(kt+1);
        const float* a_s = sm + (kt&1)*NT_STAGE;
        const float* b_s = a_s + 128*AST;
#pragma unroll
        for (int ks = 0; ks < 4; ks++) {
            uint32_t af[4][4], bf[4][2];
            int kc = ks*8 + 2*t;
            LOAD_AFRAG(a_s, af, kc, CA)
#pragma unroll
            for (int nt = 0; nt < 4; nt++) {
                int nb = wn*32 + nt*8 + g;
                float2 bb = *(const float2*)&b_s[nb*AST + kc];
                bf[nt][0] = opnd<CB>(bb.x); bf[nt][1] = opnd<CB>(bb.y);
            }
#pragma unroll
            for (int mt = 0; mt < 4; mt++)
#pragma unroll
                for (int nt = 0; nt < 4; nt++)
                    mma8(acc[mt][nt], af[mt], bf[nt]);
        }
    }

    int row0 = blockIdx.y*128 + wm*64 + g;
    int col0 = blockIdx.x*128 + wn*32 + 2*t;
#pragma unroll
    for (int nt = 0; nt < 4; nt++) {
        int c = col0 + nt*8;
        float2 bv = make_float2(0.f, 0.f);
        if (bias) bv = *(const float2*)&bias[c];
#pragma unroll
        for (int mt = 0; mt < 4; mt++) {
            int r = row0 + mt*16;
            float2 o0, o1;
            if (EXPO) {
                o0.x = tfr(__expf(alpha*acc[mt][nt][0]));
                o0.y = tfr(__expf(alpha*acc[mt][nt][1]));
                o1.x = tfr(__expf(alpha*acc[mt][nt][2]));
                o1.y = tfr(__expf(alpha*acc[mt][nt][3]));
            } else {
                o0.x = alpha*acc[mt][nt][0] + bv.x;  o0.y = alpha*acc[mt][nt][1] + bv.y;
                o1.x = alpha*acc[mt][nt][2] + bv.x;  o1.y = alpha*acc[mt][nt][3] + bv.y;
                if (RO) {
                    o0.x = tfr(o0.x); o0.y = tfr(o0.y);
                    o1.x = tfr(o1.x); o1.y = tfr(o1.y);
                }
            }
            *(float2*)&C[(size_t)r*ldc + c]     = o0;
            *(float2*)&C[(size_t)(r+8)*ldc + c] = o1;
        }
    }
}

// C = A@B, batched; ZS: scale output row r by 1/Zrow[z*NC+r]; RO: round output.
template<bool CA, bool CB, bool RO, bool ZS>
__global__ void __launch_bounds__(256, 2) tgemm_nn(
    const float* __restrict__ A, int lda, long soA, long siA,
    const float* __restrict__ Bm, int ldb, long soB, long siB,
    const float* __restrict__ Zrow,
    float* __restrict__ C, int ldc, long soC, long siC,
    int inner, int K)
{
    extern __shared__ float sm[];
    int z = blockIdx.z;
    int zo = z / inner, zi = z - zo * inner;
    A  += (size_t)zo*soA + (size_t)zi*siA;
    Bm += (size_t)zo*soB + (size_t)zi*siB;
    C  += (size_t)zo*soC + (size_t)zi*siC;

    int tid  = threadIdx.x;
    int wid  = tid >> 5, lane = tid & 31;
    int g = lane >> 2, t = lane & 3;
    int wm = wid & 1, wn = wid >> 1;

    int lr = tid >> 3;
    int lc = (tid & 7) << 2;
    const float* Ab = A + (size_t)(blockIdx.y*128 + lr)*lda + lc;
    int br = tid >> 5;
    int bc = (tid & 31) << 2;
    const float* Bb = Bm + blockIdx.x*128 + bc;

    float acc[4][4][4] = {};
    int KT = K >> 5;

#define NN_LOAD(KT_)                                                      \
    {                                                                     \
        float* a_s = sm + ((KT_)&1)*NN_STAGE;                             \
        float* b_s = a_s + 128*AST;                                       \
        _Pragma("unroll")                                                 \
        for (int i = 0; i < 4; i++) {                                     \
            cpa16(&a_s[(lr + 32*i)*AST + lc], Ab + (size_t)(32*i)*lda + (KT_)*32); \
            cpa16(&b_s[(br + 8*i)*BSTN + bc], Bb + (size_t)((KT_)*32 + br + 8*i)*ldb); \
        }                                                                 \
        cp_commit();                                                      \
    }

    NN_LOAD(0);

    for (int kt = 0; kt < KT; kt++) {
        cp_wait0();
        __syncthreads();
        if (kt + 1 < KT) NN_LOAD(kt+1);
        const float* a_s = sm + (kt&1)*NN_STAGE;
        const float* b_s = a_s + 128*AST;
#pragma unroll
        for (int ks = 0; ks < 4; ks++) {
            uint32_t af[4][4], bf[4][2];
            int kc = ks*8 + 2*t;
            LOAD_AFRAG(a_s, af, kc, CA)
#pragma unroll
            for (int nt = 0; nt < 4; nt++) {
                int nb = wn*32 + nt*8 + g;
                bf[nt][0] = opnd<CB>(b_s[kc*BSTN + nb]);
                bf[nt][1] = opnd<CB>(b_s[(kc+1)*BSTN + nb]);
            }
#pragma unroll
            for (int mt = 0; mt < 4; mt++)
#pragma unroll
                for (int nt = 0; nt < 4; nt++)
                    mma8(acc[mt][nt], af[mt], bf[nt]);
        }
    }

    int row0 = blockIdx.y*128 + wm*64 + g;
    int col0 = blockIdx.x*128 + wn*32 + 2*t;
    float zi0[4], zi1[4];
    if (ZS) {
#pragma unroll
        for (int mt = 0; mt < 4; mt++) {
            zi0[mt] = 1.f / Zrow[(size_t)blockIdx.z*NC + row0 + mt*16];
            zi1[mt] = 1.f / Zrow[(size_t)blockIdx.z*NC + row0 + mt*16 + 8];
        }
    }
#pragma unroll
    for (int nt = 0; nt < 4; nt++) {
        int c = col0 + nt*8;
#pragma unroll
        for (int mt = 0; mt < 4; mt++) {
            int r = row0 + mt*16;
            float o0 = acc[mt][nt][0], o1 = acc[mt][nt][1];
            float o2 = acc[mt][nt][2], o3 = acc[mt][nt][3];
            if (ZS) { o0 *= zi0[mt]; o1 *= zi0[mt]; o2 *= zi1[mt]; o3 *= zi1[mt]; }
            if (RO) { o0 = tfr(o0); o1 = tfr(o1); o2 = tfr(o2); o3 = tfr(o3); }
            *(float2*)&C[(size_t)r*ldc + c]     = make_float2(o0, o1);
            *(float2*)&C[(size_t)(r+8)*ldc + c] = make_float2(o2, o3);
        }
    }
}

// --------- tension partials + per-head rowsums from raw e ------------------
// Grid (NC, BB), 256 thr. Pass 1: Z_h(q)=sum_k e; pass 2 (L1-hot): partials.
__global__ void __launch_bounds__(256) k_tens(const float* __restrict__ E) {
    __shared__ float zs[8*256];
    __shared__ float zinv[8];
    int q = blockIdx.x, b = blockIdx.y;
    int tid = threadIdx.x, w = tid >> 5, lane = tid & 31;
    const float* base = E + (size_t)b*8*NC*NC + (size_t)q*NC;
    float za[8] = {};
    for (int k = tid; k < 2048; k += 256) {
#pragma unroll
        for (int h = 0; h < 8; h++) za[h] += __ldg(&base[(size_t)h*NC*NC + k]);
    }
#pragma unroll
    for (int h = 0; h < 8; h++) zs[h*256 + tid] = za[h];
    __syncthreads();
    {
        float s = 0.f;
#pragma unroll
        for (int j = 0; j < 8; j++) s += zs[w*256 + j*32 + lane];
#pragma unroll
        for (int o = 16; o > 0; o >>= 1) s += __shfl_xor_sync(0xffffffffu, s, o);
        if (lane == 0) {
            g_rowsum[(b*8 + w)*NC + q] = s;
            zinv[w] = 0.125f / s;
        }
    }
    __syncthreads();
    const float mu0 = 1.f / 2048.f;
    float zv[8];
#pragma unroll
    for (int h = 0; h < 8; h++) zv[h] = zinv[h];
    float s1 = 0.f, s2 = 0.f;
    for (int k = tid; k < 2048; k += 256) {
        float m = 0.f;
#pragma unroll
        for (int h = 0; h < 8; h++) m += __ldg(&base[(size_t)h*NC*NC + k]) * zv[h];
        s1 += m;
        float d = m - mu0;
        s2 += d * d;
    }
    float* r1 = zs; float* r2 = zs + 256;
    r1[tid] = s1; r2[tid] = s2; __syncthreads();
    for (int st = 128; st > 0; st >>= 1) {
        if (tid < st) { r1[tid] += r1[tid+st]; r2[tid] += r2[tid+st]; }
        __syncthreads();
    }
    if (tid == 0) { int bq = b*2048 + q; g_part1[bq] = r1[0]; g_part2[bq] = r2[0]; }
}

__global__ void k_tred() {
    __shared__ float r1[1024], r2[1024];
    int t = threadIdx.x;
    float s1 = 0.f, s2 = 0.f;
    for (int i = t; i < BB*NC; i += 1024) { s1 += g_part1[i]; s2 += g_part2[i]; }
    r1[t] = s1; r2[t] = s2; __syncthreads();
    for (int st = 512; st > 0; st >>= 1) {
        if (t < st) { r1[t] += r1[t+st]; r2[t] += r2[t+st]; }
        __syncthreads();
    }
    if (t == 0) {
        double Ne = 8388608.0;
        double S1 = (double)r1[0], D2 = (double)r2[0];
        double mu0 = 1.0 / 2048.0;
        double mu  = S1 / Ne;
        double var = (D2 - Ne * (mu - mu0) * (mu - mu0)) / (Ne - 1.0);
        if (var < 0.0) var = 0.0;
        g_tension += (float)sqrt(var);
    }
}

__global__ void k_addln(const float* __restrict__ g, const float* __restrict__ bta) {
    __shared__ float red[256];
    size_t row = blockIdx.x;
    int t = threadIdx.x;
    float v[4];
    float s = 0.f;
#pragma unroll
    for (int q = 0; q < 4; q++) {
        int d = q * 256 + t;
        v[q] = g_cellsB[row*DD + d] + g_tmp[row*DD + d];
        s += v[q];
    }
    red[t] = s; __syncthreads();
    for (int st = 128; st > 0; st >>= 1) {
        if (t < st) red[t] += red[t + st];
        __syncthreads();
    }
    float mu = red[0] * (1.f/1024.f);
    __syncthreads();
    float s2 = 0.f;
#pragma unroll
    for (int q = 0; q < 4; q++) { float d = v[q] - mu; s2 += d * d; }
    red[t] = s2; __syncthreads();
    for (int st = 128; st > 0; st >>= 1) {
        if (t < st) red[t] += red[t + st];
        __syncthreads();
    }
    float var  = red[0] * (1.f/1024.f);
    float rstd = rsqrtf(var + 1e-5f);
#pragma unroll
    for (int q = 0; q < 4; q++) {
        int d = q * 256 + t;
        g_cellsB[row*DD + d] = (v[q] - mu) * rstd * g[d] + bta[d];
    }
}

__global__ void k_twrite(float* __restrict__ out) { out[0] = g_tension * 0.5f; }

// ------------------------------- host launch -------------------------------
extern "C" void kernel_launch(void* const* d_in, const int* in_sizes, int n_in,
                              void* d_out, int out_size) {
    const float* x           = (const float*)d_in[0];
    const float* amp_real    = (const float*)d_in[1];
    const float* amp_imag    = (const float*)d_in[2];
    const float* coin_real   = (const float*)d_in[3];
    const float* coin_imag   = (const float*)d_in[4];
    const float* cell_emb    = (const float*)d_in[5];
    const float* fsigns      = (const float*)d_in[6];
    const float* w_in        = (const float*)d_in[7];
    const float* b_in        = (const float*)d_in[8];
    const float* attn_in_w   = (const float*)d_in[9];
    const float* attn_in_b   = (const float*)d_in[10];
    const float* attn_out_w  = (const float*)d_in[11];
    const float* attn_out_b  = (const float*)d_in[12];
    const float* ln_g        = (const float*)d_in[13];
    const float* ln_b        = (const float*)d_in[14];
    const float* w_out       = (const float*)d_in[15];
    const float* b_out       = (const float*)d_in[16];
    const int*   step        = (const int*)d_in[17];
    float* out = (float*)d_out;

    float *p_ar0, *p_ai0, *p_ar1, *p_ai1, *p_cells, *p_cellsB, *p_qkv, *p_scores,
          *p_av, *p_tmp, *p_wqkv, *p_wout, *p_wfin, *p_rowsum;
    cudaGetSymbolAddress((void**)&p_ar0,    g_ampr0);
    cudaGetSymbolAddress((void**)&p_ai0,    g_ampi0);
    cudaGetSymbolAddress((void**)&p_ar1,    g_ampr1);
    cudaGetSymbolAddress((void**)&p_ai1,    g_ampi1);
    cudaGetSymbolAddress((void**)&p_cells,  g_cells);
    cudaGetSymbolAddress((void**)&p_cellsB, g_cellsB);
    cudaGetSymbolAddress((void**)&p_qkv,    g_qkv);
    cudaGetSymbolAddress((void**)&p_scores, g_scores);
    cudaGetSymbolAddress((void**)&p_av,     g_av);
    cudaGetSymbolAddress((void**)&p_tmp,    g_tmp);
    cudaGetSymbolAddress((void**)&p_wqkv,   g_wqkv);
    cudaGetSymbolAddress((void**)&p_wout,   g_wout);
    cudaGetSymbolAddress((void**)&p_wfin,   g_wfin);
    cudaGetSymbolAddress((void**)&p_rowsum, g_rowsum);

    const int nt_smem = NT_STAGE*2*(int)sizeof(float);  // 81920
    const int nn_smem = NN_STAGE*2*(int)sizeof(float);  // 74752
    const int fr_smem = (128*128 + 1024)*(int)sizeof(float); // 69632
    static int attr_done = 0;
    if (!attr_done) {
        cudaFuncSetAttribute(tgemm_nt<true,false,false,true>,   cudaFuncAttributeMaxDynamicSharedMemorySize, nt_smem);
        cudaFuncSetAttribute(tgemm_nt<false,false,true,false>,  cudaFuncAttributeMaxDynamicSharedMemorySize, nt_smem);
        cudaFuncSetAttribute(tgemm_nt<false,false,false,false>, cudaFuncAttributeMaxDynamicSharedMemorySize, nt_smem);
        cudaFuncSetAttribute(tgemm_nt<true,false,false,false>,  cudaFuncAttributeMaxDynamicSharedMemorySize, nt_smem);
        cudaFuncSetAttribute(tgemm_nn<false,false,true,true>,   cudaFuncAttributeMaxDynamicSharedMemorySize, nn_smem);
        cudaFuncSetAttribute(k_frust, cudaFuncAttributeMaxDynamicSharedMemorySize, fr_smem);
        attr_done = 1;
    }

    // ---- weight round-copy (tf32, idempotent vs in-GEMM cvt) ----
    {
        int n4a = 2*D3*DD/4, n4b = 2*DD*DD/4, n4c = INDIM*DD/4;
        k_roundcpy<<<(n4a+255)/256, 256>>>(p_wqkv, attn_in_w, n4a);
        k_roundcpy<<<(n4b+255)/256, 256>>>(p_wout, attn_out_w, n4b);
        k_roundcpy<<<(n4c+255)/256, 256>>>(p_wfin, w_out, n4c);
    }

    // ---- update_cells preamble ----
    k_xmean<<<1, 256>>>(x, BB * INDIM);

    k_walkp<<<NC, 256>>>(amp_real, amp_imag, p_ar0, p_ai0, coin_real, coin_imag);
    k_ptot<<<1, 1024>>>();
    k_inject<<<NC, 512>>>(cell_emb, p_cells);
    k_walkp<<<NC, 256>>>(p_ar0, p_ai0, p_ar1, p_ai1, coin_real, coin_imag);
    k_ptot<<<1, 1024>>>();
    k_inject<<<NC, 512>>>(p_cells, p_cells);

    k_frust<<<8, 128, fr_smem>>>(fsigns);
    k_wave<<<NC, 256>>>(step);
    k_morph<<<32, 32>>>(step);
    k_fmean<<<dim3(8, 8), 128>>>();
    k_faction<<<NC, 256>>>(step);

    // ---- transformer body ----
    k_xproj<<<256, 256>>>(x, w_in, b_in);
    k_bcast<<<BB*NC, 256>>>();

    const float inv_sqrt_hd = 0.0883883476483184f; // 1/sqrt(128)
    for (int l = 0; l < 2; l++) {
        // qkv = cellsB @ Wqkv^T + b : [4096,3072] K=1024; output tf32-rounded
        tgemm_nt<true,false,false,true><<<dim3(24, 32, 1), 256, nt_smem>>>(
            p_cellsB, DD, 0, 0,
            p_wqkv + (size_t)l*D3*DD, DD, 0, 0,
            attn_in_b + (size_t)l*D3,
            p_qkv, D3, 0, 0, 1, DD, 1.f);

        // scores -> raw e = tf32(exp(qk/sqrt(hd))), zero-cvt inner loop
        tgemm_nt<false,false,true,false><<<dim3(16, 16, 16), 256, nt_smem>>>(
            p_qkv,        D3, (long)NC*D3, 128,
            p_qkv + 1024, D3, (long)NC*D3, 128,
            nullptr,
            p_scores, NC, (long)8*NC*NC, (long)NC*NC,
            8, HDIM, inv_sqrt_hd);

        // per-head rowsums Z + tension partials (single read of e)
        k_tens<<<dim3(NC, BB), 256>>>(p_scores);
        k_tred<<<1, 1024>>>();

        // av = (e @ V) / Z : zero-cvt; epilogue row-scale + round
        tgemm_nn<false,false,true,true><<<dim3(1, 16, 16), 256, nn_smem>>>(
            p_scores,     NC, (long)8*NC*NC, (long)NC*NC,
            p_qkv + 2048, D3, (long)NC*D3, 128,
            p_rowsum,
            p_av, DD, (long)NC*DD, 128,
            8, NC);

        // out-proj: both operands pre-rounded; output exact (residual)
        tgemm_nt<false,false,false,false><<<dim3(8, 32, 1), 256, nt_smem>>>(
            p_av, DD, 0, 0,
            p_wout + (size_t)l*DD*DD, DD, 0, 0,
            attn_out_b + (size_t)l*DD,
            p_tmp, DD, 0, 0, 1, DD, 1.f);

        k_addln<<<BB*NC, 256>>>(ln_g + (size_t)l*DD, ln_b + (size_t)l*DD);
    }

    // final projection: [4096,512] K=1024 -> d_out (B pre-rounded)
    tgemm_nt<true,false,false,false><<<dim3(4, 32, 1), 256, nt_smem>>>(
        p_cellsB, DD, 0, 0,
        p_wfin, DD, 0, 0,
        b_out,
        out, INDIM, 0, 0, 1, DD, 1.f);

    if (out_size >= BB*NC*INDIM + 1) {
        k_twrite<<<1, 1>>>(out + (size_t)BB*NC*INDIM);
    }
}

// round 8
// speedup vs baseline: 1.6278x; 1.0467x over previous
#include <cuda_runtime.h>
#include <math.h>
#include <stdint.h>

#define NC    2048
#define DD    1024
#define HD2   512
#define BB    2
#define HH    8
#define HDIM  128
#define D3    3072
#define INDIM 512

// ----------------------------- device scratch -----------------------------
__device__ float g_ampr0[NC*2*DD];
__device__ float g_ampi0[NC*2*DD];
__device__ float g_ampr1[NC*2*DD];
__device__ float g_ampi1[NC*2*DD];
__device__ float g_probs[NC];
__device__ float g_ph[NC];
__device__ float g_cells[NC*DD];
__device__ float g_fmean[8*DD];
__device__ float g_xproj[BB*DD];
__device__ float g_cellsB[BB*NC*DD];
__device__ float g_qkv[(size_t)BB*NC*D3];
__device__ float g_scores[(size_t)BB*HH*NC*NC];   // raw exp(S), 256 MiB
__device__ float g_rowsum[BB*HH*NC];
__device__ float g_av[(size_t)BB*NC*DD];
__device__ float g_tmp[(size_t)BB*NC*DD];
__device__ float g_part1[BB*NC];
__device__ float g_part2[BB*NC];
__device__ float g_wqkv[2*D3*DD];     // tf32-rounded attn_in_w
__device__ float g_wout[2*DD*DD];     // tf32-rounded attn_out_w
__device__ float g_wfin[INDIM*DD];    // tf32-rounded w_out
__device__ float g_xmean;
__device__ float g_ptot;
__device__ float g_tension;

// ----------------------------- small kernels ------------------------------
__global__ void k_xmean(const float* __restrict__ x, int n) {
    __shared__ float red[256];
    float s = 0.f;
    for (int i = threadIdx.x; i < n; i += 256) s += x[i];
    red[threadIdx.x] = s; __syncthreads();
    for (int st = 128; st > 0; st >>= 1) {
        if (threadIdx.x < st) red[threadIdx.x] += red[threadIdx.x + st];
        __syncthreads();
    }
    if (threadIdx.x == 0) { g_xmean = red[0] / (float)n; g_tension = 0.f; }
}

__device__ __forceinline__ uint32_t f2tf32(float x) {
    uint32_t r; asm("cvt.rna.tf32.f32 %0, %1;" : "=r"(r) : "f"(x)); return r;
}
__device__ __forceinline__ float tfr(float x) { return __uint_as_float(f2tf32(x)); }

// round-copy weights to tf32 (idempotent w.r.t. in-GEMM cvt)
__global__ void k_roundcpy(float* __restrict__ dst, const float* __restrict__ src, int n4) {
    int i = blockIdx.x * 256 + threadIdx.x;
    if (i < n4) {
        float4 v = ((const float4*)src)[i];
        v.x = tfr(v.x); v.y = tfr(v.y); v.z = tfr(v.z); v.w = tfr(v.w);
        ((float4*)dst)[i] = v;
    }
}

// fused quantum-walk step + probs/phase reduction (norm skipped: scale-inv)
__global__ void k_walkp(const float* __restrict__ inr, const float* __restrict__ ini,
                        float* __restrict__ outr, float* __restrict__ outi,
                        const float* __restrict__ cr, const float* __restrict__ ci) {
    __shared__ float rp[256], rh[256];
    int n = blockIdx.x;
    float c00r=cr[0], c01r=cr[1], c10r=cr[2], c11r=cr[3];
    float c00i=ci[0], c01i=ci[1], c10i=ci[2], c11i=ci[3];
    float phi = g_xmean * 0.1f;
    float pc = cosf(phi), ps = sinf(phi);
    int m[11];
#pragma unroll
    for (int j = 0; j < 11; j++) m[j] = n ^ (1 << j);
    float pacc = 0.f, hacc = 0.f;
#pragma unroll
    for (int q = 0; q < 4; q++) {
        int d  = q * 256 + threadIdx.x;
        int i0 = (n * 2) * DD + d, i1 = i0 + DD;
        float a0r = inr[i0], a0i = ini[i0], a1r = inr[i1], a1i = ini[i1];
        float n0r = c00r*a0r - c00i*a0i + c01r*a1r - c01i*a1i;
        float n0i = c00r*a0i + c00i*a0r + c01r*a1i + c01i*a1r;
        float sr = 0.f, si = 0.f;
#pragma unroll
        for (int j = 0; j < 11; j++) {
            int b0 = (m[j] * 2) * DD + d, b1 = b0 + DD;
            float x0r = inr[b0], x0i = ini[b0], x1r = inr[b1], x1i = ini[b1];
            sr += c10r*x0r - c10i*x0i + c11r*x1r - c11i*x1i;
            si += c10r*x0i + c10i*x0r + c11r*x1i + c11i*x1r;
        }
        float n1r = sr * (1.f/11.f), n1i = si * (1.f/11.f);
        float o0r = n0r*pc - n0i*ps, o0i = n0r*ps + n0i*pc;
        float o1r = n1r*pc - n1i*ps, o1i = n1r*ps + n1i*pc;
        outr[i0] = o0r;  outi[i0] = o0i;
        outr[i1] = o1r;  outi[i1] = o1i;
        pacc += o0r*o0r + o0i*o0i + o1r*o1r + o1i*o1i;
        hacc += atan2f(o0i + o1i, o0r + o1r);
    }
    rp[threadIdx.x] = pacc; rh[threadIdx.x] = hacc; __syncthreads();
    for (int st = 128; st > 0; st >>= 1) {
        if (threadIdx.x < st) { rp[threadIdx.x] += rp[threadIdx.x+st]; rh[threadIdx.x] += rh[threadIdx.x+st]; }
        __syncthreads();
    }
    if (threadIdx.x == 0) { g_probs[n] = rp[0]; g_ph[n] = rh[0] * (1.f/1024.f); }
}

__global__ void k_ptot() {
    __shared__ float red[1024];
    int t = threadIdx.x;
    red[t] = g_probs[t] + g_probs[t + 1024];
    __syncthreads();
    for (int st = 512; st > 0; st >>= 1) {
        if (t < st) red[t] += red[t + st];
        __syncthreads();
    }
    if (t == 0) g_ptot = red[0];
}

__global__ void k_inject(const float* __restrict__ src, float* __restrict__ dst) {
    int i = blockIdx.x, d = threadIdx.x;      // 512 threads
    float inv = 1.f / (g_ptot + 1e-8f);
    float p = g_probs[i] * inv;
    float interf = 0.f;
#pragma unroll
    for (int k = 0; k < 6; k++) interf += p - g_probs[i ^ (1 << k)] * inv;
    interf *= 0.03f;
    float phc = g_ph[i] * 0.3f;
    float c = cosf(phc), s = sinf(phc);
    float scale = 0.8f + 0.4f * p;
    float t1 = src[i*DD + d]       * scale;
    float t2 = src[i*DD + HD2 + d] * scale;
    dst[i*DD + d]       = 0.5f*(t1*c - t2*s) + 0.5f*t1 + interf;
    dst[i*DD + HD2 + d] = 0.5f*(t1*s + t2*c) + 0.5f*t2 + interf;
}

// smem-resident per-column frustration recurrence; 8 blocks x 128 columns
__global__ void k_frust(const float* __restrict__ fs) {
    extern __shared__ float fsm[];                 // sc[128*128] + sfs[1024]
    float* sc  = fsm;
    float* sfs = fsm + 128*128;
    int t = threadIdx.x;
    int col = blockIdx.x * 128 + t;
    for (int r = 0; r < 128; r++) sc[r*128 + t] = g_cells[r*DD + col];
    for (int i = t; i < 1024; i += 128) sfs[i] = fs[i];
    __syncthreads();
    float p0 = g_cells[128*DD + col];
    float p1 = g_cells[256*DD + col];
    float p2 = g_cells[512*DD + col];
    for (int i = 0; i < 128; i++) {
        float n0=0.f, n1=0.f, n2=0.f;
        if (i + 1 < 128) {
            n0 = g_cells[((i+1)^128)*DD + col];
            n1 = g_cells[((i+1)^256)*DD + col];
            n2 = g_cells[((i+1)^512)*DD + col];
        }
        float fi = sfs[i];
        float infl = fi*(sfs[i^128]*p0 + sfs[i^256]*p1 + sfs[i^512]*p2);
#pragma unroll
        for (int b = 0; b < 7; b++) {
            int j = i ^ (1 << b);
            infl += fi * sfs[j] * sc[j*128 + t];
        }
        sc[i*128 + t] = 0.85f * sc[i*128 + t] + 0.015f * infl;
        p0 = n0; p1 = n1; p2 = n2;
    }
    for (int r = 0; r < 128; r++) g_cells[r*DD + col] = sc[r*128 + t];
}

__global__ void k_wave(const int* __restrict__ step) {
    int i = blockIdx.x;
    float st  = (float)step[0];
    float fwd = fmodf(st * 0.15f, 2048.f);
    float bwd = fmodf(2048.f - st * 0.15f, 2048.f);
    float fi  = (float)i;
    float c1 = coshf((fi - fwd) * 0.5f), c2 = coshf((fi - bwd) * 0.5f);
    float amp = 1.f/(c1*c1) + 1.f/(c2*c2);
    float f = 1.f + 0.03f * amp;
#pragma unroll
    for (int q = 0; q < 4; q++) {
        int d = q * 256 + threadIdx.x;
        g_cells[i*DD + d] *= f;
    }
}

// morph: 128 blocks x 64 threads = 8 columns/block x 8 k-threads/column.
// MUFU.TANH work spread across all SMs; shuffle-reduce (width 8) per i-step.
__global__ void k_morph(const int* __restrict__ step) {
    if (step[0] % 3 != 0) return;
    __shared__ float sv[8*48];
    int t = threadIdx.x;
    int lc = t >> 3, kt = t & 7;          // column-in-block, k-thread
    int col = blockIdx.x * 8 + lc;
    for (int k = kt; k < 48; k += 8) sv[lc*48 + k] = g_cells[k*DD + col];
    __syncwarp();
    for (int i = 0; i < 48; i++) {
        float vi = sv[lc*48 + i];
        float s = 0.f;
#pragma unroll
        for (int j = 0; j < 6; j++) s += tanhf(sv[lc*48 + kt*6 + j] - vi);
        s += __shfl_down_sync(0xffffffffu, s, 4, 8);
        s += __shfl_down_sync(0xffffffffu, s, 2, 8);
        s += __shfl_down_sync(0xffffffffu, s, 1, 8);
        if (kt == 0) sv[lc*48 + i] = 0.9f * vi + 0.1f * s * (1.f/47.f);
        __syncwarp();
    }
    for (int k = kt; k < 48; k += 8) g_cells[k*DD + col] = sv[lc*48 + k];
}

__global__ void k_fmean() {
    int f = blockIdx.x;
    int col = blockIdx.y * 128 + threadIdx.x;
    float s = 0.f;
    for (int r = 0; r < 256; r++) s += g_cells[(f*256 + r)*DD + col];
    g_fmean[f*DD + col] = s * (1.f/256.f);
}

__global__ void k_faction(const int* __restrict__ step) {
    int n = blockIdx.x;
    int f = n >> 8, r = n & 255;
    bool debate = (step[0] > 5) && (r < 64);
#pragma unroll
    for (int q = 0; q < 4; q++) {
        int col = q * 256 + threadIdx.x;
        float v = 0.85f * g_cells[n*DD + col] + 0.15f * g_fmean[f*DD + col];
        if (debate) {
            float g = 0.f;
#pragma unroll
            for (int ff = 0; ff < 8; ff++) g += g_fmean[ff*DD + col];
            v = 0.85f * v + 0.15f * (g * 0.125f);
        }
        g_cells[n*DD + col] = v;
    }
}

__global__ void k_xproj(const float* __restrict__ x, const float* __restrict__ w,
                        const float* __restrict__ b) {
    int gw   = (blockIdx.x * blockDim.x + threadIdx.x) >> 5;
    int lane = threadIdx.x & 31;
    if (gw >= BB * DD) return;
    int bi = gw / DD, j = gw % DD;
    const float* xr = x + bi * INDIM;
    const float* wr = w + (size_t)j * INDIM;
    float s = 0.f;
    for (int k = lane; k < INDIM; k += 32) s += xr[k] * wr[k];
    for (int o = 16; o > 0; o >>= 1) s += __shfl_down_sync(0xffffffffu, s, o);
    if (lane == 0) g_xproj[gw] = s + b[j];
}

__global__ void k_bcast() {
    int row = blockIdx.x;
    int b = row / NC, n = row % NC;
#pragma unroll
    for (int q = 0; q < 4; q++) {
        int d = q * 256 + threadIdx.x;
        g_cellsB[(size_t)row*DD + d] = g_cells[n*DD + d] + 0.1f * g_xproj[b*DD + d];
    }
}

// ------------------------- tf32 tensor-core GEMMs -------------------------
__device__ __forceinline__ void mma8(float* c, const uint32_t* a, const uint32_t* b) {
    asm volatile(
        "mma.sync.aligned.m16n8k8.row.col.f32.tf32.tf32.f32 "
        "{%0,%1,%2,%3},{%4,%5,%6,%7},{%8,%9},{%0,%1,%2,%3};"
        : "+f"(c[0]), "+f"(c[1]), "+f"(c[2]), "+f"(c[3])
        : "r"(a[0]), "r"(a[1]), "r"(a[2]), "r"(a[3]), "r"(b[0]), "r"(b[1]));
}
__device__ __forceinline__ void cpa16(float* dst, const float* src) {
    unsigned d = (unsigned)__cvta_generic_to_shared(dst);
    asm volatile("cp.async.cg.shared.global [%0], [%1], 16;\n" :: "r"(d), "l"(src));
}
__device__ __forceinline__ void cp_commit() { asm volatile("cp.async.commit_group;\n"); }
__device__ __forceinline__ void cp_wait0() { asm volatile("cp.async.wait_group 0;\n"); }

template<bool DOC>
__device__ __forceinline__ uint32_t opnd(float x) {
    return DOC ? f2tf32(x) : __float_as_uint(x);
}

#define AST 40           // smem row stride (floats) for [row][k] tiles
#define BSTN 132         // smem row stride for [k][n] tiles (NN B)
#define NT_STAGE (128*AST*2)
#define NN_STAGE (128*AST + 32*BSTN)

#define LOAD_AFRAG(AS, AF, KC, DOC)                                       \
    _Pragma("unroll")                                                     \
    for (int mt = 0; mt < 4; mt++) {                                      \
        int rb = wm*64 + mt*16 + g;                                       \
        float2 lo = *(const float2*)&(AS)[rb*AST + (KC)];                 \
        float2 hi = *(const float2*)&(AS)[(rb+8)*AST + (KC)];             \
        (AF)[mt][0] = opnd<DOC>(lo.x); (AF)[mt][2] = opnd<DOC>(lo.y);     \
        (AF)[mt][1] = opnd<DOC>(hi.x); (AF)[mt][3] = opnd<DOC>(hi.y);     \
    }

// C = alpha*A@W^T (+bias); EXPO: C = tf32(exp(alpha*acc)); RO: round output.
template<bool CA, bool CB, bool EXPO, bool RO>
__global__ void __launch_bounds__(256, 2) tgemm_nt(
    const float* __restrict__ A, int lda, long soA, long siA,
    const float* __restrict__ W, int ldw, long soW, long siW,
    const float* __restrict__ bias,
    float* __restrict__ C, int ldc, long soC, long siC,
    int inner, int K, float alpha)
{
    extern __shared__ float sm[];
    int z = blockIdx.z;
    int zo = z / inner, zi = z - zo * inner;
    A += (size_t)zo*soA + (size_t)zi*siA;
    W += (size_t)zo*soW + (size_t)zi*siW;
    C += (size_t)zo*soC + (size_t)zi*siC;

    int tid  = threadIdx.x;
    int wid  = tid >> 5, lane = tid & 31;
    int g = lane >> 2, t = lane & 3;
    int wm = wid & 1, wn = wid >> 1;

    int lr = tid >> 3;
    int lc = (tid & 7) << 2;
    const float* Ab = A + (size_t)(blockIdx.y*128 + lr)*lda + lc;
    const float* Wb = W + (size_t)(blockIdx.x*128 + lr)*ldw + lc;

    float acc[4][4][4] = {};
    int KT = K >> 5;

#define NT_LOAD(KT_)                                                      \
    {                                                                     \
        float* a_s = sm + ((KT_)&1)*NT_STAGE;                             \
        float* b_s = a_s + 128*AST;                                       \
        _Pragma("unroll")                                                 \
        for (int i = 0; i < 4; i++) {                                     \
            cpa16(&a_s[(lr + 32*i)*AST + lc], Ab + (size_t)(32*i)*lda + (KT_)*32); \
            cpa16(&b_s[(lr + 32*i)*AST + lc], Wb + (size_t)(32*i)*ldw + (KT_)*32); \
        }                                                                 \
        cp_commit();                                                      \
    }

    NT_LOAD(0);

    for (int kt = 0; kt < KT; kt++) {
        cp_wait0();
        __syncthreads();
        if (kt + 1 < KT) NT_LOAD(kt+1);
        const float* a_s = sm + (kt&1)*NT_STAGE;
        const float* b_s = a_s + 128*AST;
#pragma unroll
        for (int ks = 0; ks < 4; ks++) {
            uint32_t af[4][4], bf[4][2];
            int kc = ks*8 + 2*t;
            LOAD_AFRAG(a_s, af, kc, CA)
#pragma unroll
            for (int nt = 0; nt < 4; nt++) {
                int nb = wn*32 + nt*8 + g;
                float2 bb = *(const float2*)&b_s[nb*AST + kc];
                bf[nt][0] = opnd<CB>(bb.x); bf[nt][1] = opnd<CB>(bb.y);
            }
#pragma unroll
            for (int mt = 0; mt < 4; mt++)
#pragma unroll
                for (int nt = 0; nt < 4; nt++)
                    mma8(acc[mt][nt], af[mt], bf[nt]);
        }
    }

    int row0 = blockIdx.y*128 + wm*64 + g;
    int col0 = blockIdx.x*128 + wn*32 + 2*t;
#pragma unroll
    for (int nt = 0; nt < 4; nt++) {
        int c = col0 + nt*8;
        float2 bv = make_float2(0.f, 0.f);
        if (bias) bv = *(const float2*)&bias[c];
#pragma unroll
        for (int mt = 0; mt < 4; mt++) {
            int r = row0 + mt*16;
            float2 o0, o1;
            if (EXPO) {
                o0.x = tfr(__expf(alpha*acc[mt][nt][0]));
                o0.y = tfr(__expf(alpha*acc[mt][nt][1]));
                o1.x = tfr(__expf(alpha*acc[mt][nt][2]));
                o1.y = tfr(__expf(alpha*acc[mt][nt][3]));
            } else {
                o0.x = alpha*acc[mt][nt][0] + bv.x;  o0.y = alpha*acc[mt][nt][1] + bv.y;
                o1.x = alpha*acc[mt][nt][2] + bv.x;  o1.y = alpha*acc[mt][nt][3] + bv.y;
                if (RO) {
                    o0.x = tfr(o0.x); o0.y = tfr(o0.y);
                    o1.x = tfr(o1.x); o1.y = tfr(o1.y);
                }
            }
            *(float2*)&C[(size_t)r*ldc + c]     = o0;
            *(float2*)&C[(size_t)(r+8)*ldc + c] = o1;
        }
    }
}

// C = A@B, batched. ZC: compute per-row Z = sum_k A (from smem, free of DRAM),
// scale output rows by 1/Z, write Z to Zout[z*NC + row]. RO: round output.
// Requires grid.x == 1 when ZC (each CTA spans the full K loop for its rows).
template<bool CA, bool CB, bool RO, bool ZC>
__global__ void __launch_bounds__(256, 2) tgemm_nn(
    const float* __restrict__ A, int lda, long soA, long siA,
    const float* __restrict__ Bm, int ldb, long soB, long siB,
    float* __restrict__ Zout,
    float* __restrict__ C, int ldc, long soC, long siC,
    int inner, int K)
{
    extern __shared__ float sm[];
    __shared__ float zs[256];
    __shared__ float zfin[128];
    int z = blockIdx.z;
    int zo = z / inner, zi = z - zo * inner;
    A  += (size_t)zo*soA + (size_t)zi*siA;
    Bm += (size_t)zo*soB + (size_t)zi*siB;
    C  += (size_t)zo*soC + (size_t)zi*siC;

    int tid  = threadIdx.x;
    int wid  = tid >> 5, lane = tid & 31;
    int g = lane >> 2, t = lane & 3;
    int wm = wid & 1, wn = wid >> 1;

    int lr = tid >> 3;
    int lc = (tid & 7) << 2;
    const float* Ab = A + (size_t)(blockIdx.y*128 + lr)*lda + lc;
    int br = tid >> 5;
    int bc = (tid & 31) << 2;
    const float* Bb = Bm + blockIdx.x*128 + bc;

    float acc[4][4][4] = {};
    float zacc = 0.f;
    int zr = tid & 127, zh = tid >> 7;    // Z-sum: row, k-half
    int KT = K >> 5;

#define NN_LOAD(KT_)                                                      \
    {                                                                     \
        float* a_s = sm + ((KT_)&1)*NN_STAGE;                             \
        float* b_s = a_s + 128*AST;                                       \
        _Pragma("unroll")                                                 \
        for (int i = 0; i < 4; i++) {                                     \
            cpa16(&a_s[(lr + 32*i)*AST + lc], Ab + (size_t)(32*i)*lda + (KT_)*32); \
            cpa16(&b_s[(br + 8*i)*BSTN + bc], Bb + (size_t)((KT_)*32 + br + 8*i)*ldb); \
        }                                                                 \
        cp_commit();                                                      \
    }

    NN_LOAD(0);

    for (int kt = 0; kt < KT; kt++) {
        cp_wait0();
        __syncthreads();
        if (kt + 1 < KT) NN_LOAD(kt+1);
        const float* a_s = sm + (kt&1)*NN_STAGE;
        const float* b_s = a_s + 128*AST;
#pragma unroll
        for (int ks = 0; ks < 4; ks++) {
            uint32_t af[4][4], bf[4][2];
            int kc = ks*8 + 2*t;
            LOAD_AFRAG(a_s, af, kc, CA)
#pragma unroll
            for (int nt = 0; nt < 4; nt++) {
                int nb = wn*32 + nt*8 + g;
                bf[nt][0] = opnd<CB>(b_s[kc*BSTN + nb]);
                bf[nt][1] = opnd<CB>(b_s[(kc+1)*BSTN + nb]);
            }
#pragma unroll
            for (int mt = 0; mt < 4; mt++)
#pragma unroll
                for (int nt = 0; nt < 4; nt++)
                    mma8(acc[mt][nt], af[mt], bf[nt]);
        }
        if (ZC) {
            const float* ap = a_s + zr*AST + zh*16;
#pragma unroll
            for (int j = 0; j < 4; j++) {
                float4 v = *(const float4*)(ap + j*4);
                zacc += v.x + v.y + v.z + v.w;
            }
        }
    }

    if (ZC) {
        zs[tid] = zacc;
        __syncthreads();
        if (tid < 128) {
            float zv = zs[tid] + zs[tid + 128];
            zfin[tid] = 1.f / zv;
            Zout[(size_t)blockIdx.z*NC + blockIdx.y*128 + tid] = zv;
        }
        __syncthreads();
    }

    int row0 = blockIdx.y*128 + wm*64 + g;
    int col0 = blockIdx.x*128 + wn*32 + 2*t;
    float zi0[4], zi1[4];
    if (ZC) {
#pragma unroll
        for (int mt = 0; mt < 4; mt++) {
            zi0[mt] = zfin[wm*64 + mt*16 + g];
            zi1[mt] = zfin[wm*64 + mt*16 + g + 8];
        }
    }
#pragma unroll
    for (int nt = 0; nt < 4; nt++) {
        int c = col0 + nt*8;
#pragma unroll
        for (int mt = 0; mt < 4; mt++) {
            int r = row0 + mt*16;
            float o0 = acc[mt][nt][0], o1 = acc[mt][nt][1];
            float o2 = acc[mt][nt][2], o3 = acc[mt][nt][3];
            if (ZC) { o0 *= zi0[mt]; o1 *= zi0[mt]; o2 *= zi1[mt]; o3 *= zi1[mt]; }
            if (RO) { o0 = tfr(o0); o1 = tfr(o1); o2 = tfr(o2); o3 = tfr(o3); }
            *(float2*)&C[(size_t)r*ldc + c]     = make_float2(o0, o1);
            *(float2*)&C[(size_t)(r+8)*ldc + c] = make_float2(o2, o3);
        }
    }
}

// --------- tension partials: single pass over e, Z from g_rowsum ----------
__global__ void __launch_bounds__(256) k_tens(const float* __restrict__ E) {
    __shared__ float r1[256], r2[256];
    __shared__ float zinv[8];
    int q = blockIdx.x, b = blockIdx.y;
    int tid = threadIdx.x;
    if (tid < 8) zinv[tid] = 0.125f / g_rowsum[(b*8 + tid)*NC + q];
    __syncthreads();
    const float* base = E + (size_t)b*8*NC*NC + (size_t)q*NC;
    const float mu0 = 1.f / 2048.f;
    float zv[8];
#pragma unroll
    for (int h = 0; h < 8; h++) zv[h] = zinv[h];
    float s1 = 0.f, s2 = 0.f;
    for (int k = tid; k < 2048; k += 256) {
        float m = 0.f;
#pragma unroll
        for (int h = 0; h < 8; h++) m += __ldg(&base[(size_t)h*NC*NC + k]) * zv[h];
        s1 += m;
        float d = m - mu0;
        s2 += d * d;
    }
    r1[tid] = s1; r2[tid] = s2; __syncthreads();
    for (int st = 128; st > 0; st >>= 1) {
        if (tid < st) { r1[tid] += r1[tid+st]; r2[tid] += r2[tid+st]; }
        __syncthreads();
    }
    if (tid == 0) { int bq = b*2048 + q; g_part1[bq] = r1[0]; g_part2[bq] = r2[0]; }
}

__global__ void k_tred() {
    __shared__ float r1[1024], r2[1024];
    int t = threadIdx.x;
    float s1 = 0.f, s2 = 0.f;
    for (int i = t; i < BB*NC; i += 1024) { s1 += g_part1[i]; s2 += g_part2[i]; }
    r1[t] = s1; r2[t] = s2; __syncthreads();
    for (int st = 512; st > 0; st >>= 1) {
        if (t < st) { r1[t] += r1[t+st]; r2[t] += r2[t+st]; }
        __syncthreads();
    }
    if (t == 0) {
        double Ne = 8388608.0;
        double S1 = (double)r1[0], D2 = (double)r2[0];
        double mu0 = 1.0 / 2048.0;
        double mu  = S1 / Ne;
        double var = (D2 - Ne * (mu - mu0) * (mu - mu0)) / (Ne - 1.0);
        if (var < 0.0) var = 0.0;
        g_tension += (float)sqrt(var);
    }
}

__global__ void k_addln(const float* __restrict__ g, const float* __restrict__ bta) {
    __shared__ float red[256];
    size_t row = blockIdx.x;
    int t = threadIdx.x;
    float v[4];
    float s = 0.f;
#pragma unroll
    for (int q = 0; q < 4; q++) {
        int d = q * 256 + t;
        v[q] = g_cellsB[row*DD + d] + g_tmp[row*DD + d];
        s += v[q];
    }
    red[t] = s; __syncthreads();
    for (int st = 128; st > 0; st >>= 1) {
        if (t < st) red[t] += red[t + st];
        __syncthreads();
    }
    float mu = red[0] * (1.f/1024.f);
    __syncthreads();
    float s2 = 0.f;
#pragma unroll
    for (int q = 0; q < 4; q++) { float d = v[q] - mu; s2 += d * d; }
    red[t] = s2; __syncthreads();
    for (int st = 128; st > 0; st >>= 1) {
        if (t < st) red[t] += red[t + st];
        __syncthreads();
    }
    float var  = red[0] * (1.f/1024.f);
    float rstd = rsqrtf(var + 1e-5f);
#pragma unroll
    for (int q = 0; q < 4; q++) {
        int d = q * 256 + t;
        g_cellsB[row*DD + d] = (v[q] - mu) * rstd * g[d] + bta[d];
    }
}

__global__ void k_twrite(float* __restrict__ out) { out[0] = g_tension * 0.5f; }

// ------------------------------- host launch -------------------------------
extern "C" void kernel_launch(void* const* d_in, const int* in_sizes, int n_in,
                              void* d_out, int out_size) {
    const float* x           = (const float*)d_in[0];
    const float* amp_real    = (const float*)d_in[1];
    const float* amp_imag    = (const float*)d_in[2];
    const float* coin_real   = (const float*)d_in[3];
    const float* coin_imag   = (const float*)d_in[4];
    const float* cell_emb    = (const float*)d_in[5];
    const float* fsigns      = (const float*)d_in[6];
    const float* w_in        = (const float*)d_in[7];
    const float* b_in        = (const float*)d_in[8];
    const float* attn_in_w   = (const float*)d_in[9];
    const float* attn_in_b   = (const float*)d_in[10];
    const float* attn_out_w  = (const float*)d_in[11];
    const float* attn_out_b  = (const float*)d_in[12];
    const float* ln_g        = (const float*)d_in[13];
    const float* ln_b        = (const float*)d_in[14];
    const float* w_out       = (const float*)d_in[15];
    const float* b_out       = (const float*)d_in[16];
    const int*   step        = (const int*)d_in[17];
    float* out = (float*)d_out;

    float *p_ar0, *p_ai0, *p_ar1, *p_ai1, *p_cells, *p_cellsB, *p_qkv, *p_scores,
          *p_av, *p_tmp, *p_wqkv, *p_wout, *p_wfin, *p_rowsum;
    cudaGetSymbolAddress((void**)&p_ar0,    g_ampr0);
    cudaGetSymbolAddress((void**)&p_ai0,    g_ampi0);
    cudaGetSymbolAddress((void**)&p_ar1,    g_ampr1);
    cudaGetSymbolAddress((void**)&p_ai1,    g_ampi1);
    cudaGetSymbolAddress((void**)&p_cells,  g_cells);
    cudaGetSymbolAddress((void**)&p_cellsB, g_cellsB);
    cudaGetSymbolAddress((void**)&p_qkv,    g_qkv);
    cudaGetSymbolAddress((void**)&p_scores, g_scores);
    cudaGetSymbolAddress((void**)&p_av,     g_av);
    cudaGetSymbolAddress((void**)&p_tmp,    g_tmp);
    cudaGetSymbolAddress((void**)&p_wqkv,   g_wqkv);
    cudaGetSymbolAddress((void**)&p_wout,   g_wout);
    cudaGetSymbolAddress((void**)&p_wfin,   g_wfin);
    cudaGetSymbolAddress((void**)&p_rowsum, g_rowsum);

    const int nt_smem = NT_STAGE*2*(int)sizeof(float);  // 81920
    const int nn_smem = NN_STAGE*2*(int)sizeof(float);  // 74752
    const int fr_smem = (128*128 + 1024)*(int)sizeof(float); // 69632
    static int attr_done = 0;
    if (!attr_done) {
        cudaFuncSetAttribute(tgemm_nt<true,false,false,true>,   cudaFuncAttributeMaxDynamicSharedMemorySize, nt_smem);
        cudaFuncSetAttribute(tgemm_nt<false,false,true,false>,  cudaFuncAttributeMaxDynamicSharedMemorySize, nt_smem);
        cudaFuncSetAttribute(tgemm_nt<false,false,false,false>, cudaFuncAttributeMaxDynamicSharedMemorySize, nt_smem);
        cudaFuncSetAttribute(tgemm_nt<true,false,false,false>,  cudaFuncAttributeMaxDynamicSharedMemorySize, nt_smem);
        cudaFuncSetAttribute(tgemm_nn<false,false,true,true>,   cudaFuncAttributeMaxDynamicSharedMemorySize, nn_smem);
        cudaFuncSetAttribute(k_frust, cudaFuncAttributeMaxDynamicSharedMemorySize, fr_smem);
        attr_done = 1;
    }

    // ---- weight round-copy (tf32, idempotent vs in-GEMM cvt) ----
    {
        int n4a = 2*D3*DD/4, n4b = 2*DD*DD/4, n4c = INDIM*DD/4;
        k_roundcpy<<<(n4a+255)/256, 256>>>(p_wqkv, attn_in_w, n4a);
        k_roundcpy<<<(n4b+255)/256, 256>>>(p_wout, attn_out_w, n4b);
        k_roundcpy<<<(n4c+255)/256, 256>>>(p_wfin, w_out, n4c);
    }

    // ---- update_cells preamble ----
    k_xmean<<<1, 256>>>(x, BB * INDIM);

    k_walkp<<<NC, 256>>>(amp_real, amp_imag, p_ar0, p_ai0, coin_real, coin_imag);
    k_ptot<<<1, 1024>>>();
    k_inject<<<NC, 512>>>(cell_emb, p_cells);
    k_walkp<<<NC, 256>>>(p_ar0, p_ai0, p_ar1, p_ai1, coin_real, coin_imag);
    k_ptot<<<1, 1024>>>();
    k_inject<<<NC, 512>>>(p_cells, p_cells);

    k_frust<<<8, 128, fr_smem>>>(fsigns);
    k_wave<<<NC, 256>>>(step);
    k_morph<<<128, 64>>>(step);
    k_fmean<<<dim3(8, 8), 128>>>();
    k_faction<<<NC, 256>>>(step);

    // ---- transformer body ----
    k_xproj<<<256, 256>>>(x, w_in, b_in);
    k_bcast<<<BB*NC, 256>>>();

    const float inv_sqrt_hd = 0.0883883476483184f; // 1/sqrt(128)
    for (int l = 0; l < 2; l++) {
        // qkv = cellsB @ Wqkv^T + b : [4096,3072] K=1024; output tf32-rounded
        tgemm_nt<true,false,false,true><<<dim3(24, 32, 1), 256, nt_smem>>>(
            p_cellsB, DD, 0, 0,
            p_wqkv + (size_t)l*D3*DD, DD, 0, 0,
            attn_in_b + (size_t)l*D3,
            p_qkv, D3, 0, 0, 1, DD, 1.f);

        // scores -> raw e = tf32(exp(qk/sqrt(hd))), zero-cvt inner loop
        tgemm_nt<false,false,true,false><<<dim3(16, 16, 16), 256, nt_smem>>>(
            p_qkv,        D3, (long)NC*D3, 128,
            p_qkv + 1024, D3, (long)NC*D3, 128,
            nullptr,
            p_scores, NC, (long)8*NC*NC, (long)NC*NC,
            8, HDIM, inv_sqrt_hd);

        // av = (e @ V) / Z : Z computed in-kernel from smem (no extra DRAM);
        // writes Z to g_rowsum for the tension pass
        tgemm_nn<false,false,true,true><<<dim3(1, 16, 16), 256, nn_smem>>>(
            p_scores,     NC, (long)8*NC*NC, (long)NC*NC,
            p_qkv + 2048, D3, (long)NC*D3, 128,
            p_rowsum,
            p_av, DD, (long)NC*DD, 128,
            8, NC);

        // tension partials: single read of e (Z already available)
        k_tens<<<dim3(NC, BB), 256>>>(p_scores);
        k_tred<<<1, 1024>>>();

        // out-proj: both operands pre-rounded; output exact (residual)
        tgemm_nt<false,false,false,false><<<dim3(8, 32, 1), 256, nt_smem>>>(
            p_av, DD, 0, 0,
            p_wout + (size_t)l*DD*DD, DD, 0, 0,
            attn_out_b + (size_t)l*DD,
            p_tmp, DD, 0, 0, 1, DD, 1.f);

        k_addln<<<BB*NC, 256>>>(ln_g + (size_t)l*DD, ln_b + (size_t)l*DD);
    }

    // final projection: [4096,512] K=1024 -> d_out (B pre-rounded)
    tgemm_nt<true,false,false,false><<<dim3(4, 32, 1), 256, nt_smem>>>(
        p_cellsB, DD, 0, 0,
        p_wfin, DD, 0, 0,
        b_out,
        out, INDIM, 0, 0, 1, DD, 1.f);

    if (out_size >= BB*NC*INDIM + 1) {
        k_twrite<<<1, 1>>>(out + (size_t)BB*NC*INDIM);
    }
}